// round 1
// baseline (speedup 1.0000x reference)
#include <cuda_runtime.h>
#include <math.h>

#define NN 10000
#define EE 320000
#define DD 128

// ---------------- static device scratch (no allocations allowed) ----------------
// projections: 0 V1h, 1 V2h, 2 P1h, 3 P2h, 4 P3h, 5 D1h, 6 D2h, 7 Th
__device__ float g_proj[8][NN * DD];
__device__ float g_enew[(size_t)EE * DD];   // e_new rows (only needed for masked edges)
__device__ float g_facc[NN * DD];           // += c * e_new  (== -fab, since f = f0 - fab)
__device__ int   g_cnt0[NN];                // # edges with dst=v and smask==0
__device__ int   g_mlist[EE];               // compacted list of smask==1 edges
__device__ int   g_mcount;
// transposed weights: slots 0..8 are 128x128 (Wt[k*128+j] = W[j*128+k]),
// slot 9 (offset 9*16384) is W_T transposed 256x128.
__device__ float g_wt[11 * DD * DD];

__device__ __forceinline__ float lrelu(float x) { return x > 0.f ? x : 0.01f * x; }
__device__ __forceinline__ float relu_(float x) { return x > 0.f ? x : 0.f; }

// ---------------- zero scratch ----------------
__global__ void k_zero() {
    int i = blockIdx.x * blockDim.x + threadIdx.x;
    int stride = gridDim.x * blockDim.x;
    for (int t = i; t < NN * DD; t += stride) g_facc[t] = 0.f;
    for (int t = i; t < NN; t += stride) g_cnt0[t] = 0;
    if (i == 0) g_mcount = 0;
}

// ---------------- transpose all weights into g_wt ----------------
__global__ void k_wt(const float* W0, const float* W1, const float* W2, const float* W3,
                     const float* W4, const float* W5, const float* W6, const float* W7,
                     const float* W8, const float* WT) {
    const float* Wp[9] = {W0, W1, W2, W3, W4, W5, W6, W7, W8};
    int i = blockIdx.x * blockDim.x + threadIdx.x;
    int stride = gridDim.x * blockDim.x;
    for (int t = i; t < 9 * DD * DD; t += stride) {
        int s = t >> 14, r = t & 16383;
        int k = r >> 7, j = r & 127;
        g_wt[t] = Wp[s][j * 128 + k];
    }
    for (int t = i; t < 256 * 128; t += stride) {
        int k = t >> 7, j = t & 127;
        g_wt[9 * DD * DD + t] = WT[j * 256 + k];
    }
}

// ---------------- histogram + compaction ----------------
__global__ void k_count(const int* __restrict__ smask, const int* __restrict__ dst) {
    int i = blockIdx.x * blockDim.x + threadIdx.x;
    int stride = gridDim.x * blockDim.x;
    for (int e = i; e < EE; e += stride) {
        if (smask[e] == 0) {
            atomicAdd(&g_cnt0[dst[e]], 1);
        } else {
            int ix = atomicAdd(&g_mcount, 1);
            g_mlist[ix] = e;
        }
    }
}

// ---------------- node GEMMs: out[32 rows x 128 ch] per block ----------------
// grid.y = pair 0..7. pair 7: Th = concat(h,d) @ W_T^T + b_T (K=256)
__global__ void k_nodegemm(const float* __restrict__ h, const float* __restrict__ p,
                           const float* __restrict__ dv,
                           const float* bV1, const float* bV2, const float* bP1,
                           const float* bP2, const float* bP3, const float* bD1,
                           const float* bD2, const float* bT) {
    extern __shared__ float sm[];
    int pair = blockIdx.y;
    const float *X, *X2 = nullptr, *bias;
    int wslot;
    float* outp;
    switch (pair) {
        case 0: X = h;  wslot = 0; bias = bV1; outp = g_proj[0]; break;
        case 1: X = h;  wslot = 1; bias = bV2; outp = g_proj[1]; break;
        case 2: X = p;  wslot = 2; bias = bP1; outp = g_proj[2]; break;
        case 3: X = p;  wslot = 3; bias = bP2; outp = g_proj[3]; break;
        case 4: X = p;  wslot = 4; bias = bP3; outp = g_proj[4]; break;
        case 5: X = dv; wslot = 5; bias = bD1; outp = g_proj[5]; break;
        case 6: X = dv; wslot = 6; bias = bD2; outp = g_proj[6]; break;
        default: X = h; X2 = dv; wslot = 9; bias = bT; outp = g_proj[7]; break;
    }
    const int K = (pair == 7) ? 256 : 128;
    const int K4 = K / 4;
    float* Ws = sm;            // K rows, stride 132 floats (33 float4)
    float* As = sm + K * 132;  // 32 rows x K

    const float* Gw = g_wt + wslot * DD * DD;
    for (int idx = threadIdx.x; idx < K * 32; idx += 256) {
        int k = idx >> 5, j4 = idx & 31;
        ((float4*)Ws)[k * 33 + j4] = ((const float4*)Gw)[idx];
    }
    int r0 = blockIdx.x * 32;
    for (int idx = threadIdx.x; idx < 32 * K4; idx += 256) {
        int e = idx / K4, k4 = idx % K4;
        int row = r0 + e;
        float4 v = make_float4(0.f, 0.f, 0.f, 0.f);
        if (row < NN) {
            if (k4 < 32) v = ((const float4*)X)[row * 32 + k4];
            else         v = ((const float4*)X2)[row * 32 + (k4 - 32)];
        }
        ((float4*)As)[e * K4 + k4] = v;
    }
    __syncthreads();

    int w = threadIdx.x >> 5, l = threadIdx.x & 31;
    float acc[4][4] = {};
    for (int k4 = 0; k4 < K4; ++k4) {
        float4 wv0 = ((float4*)Ws)[(4 * k4 + 0) * 33 + l];
        float4 wv1 = ((float4*)Ws)[(4 * k4 + 1) * 33 + l];
        float4 wv2 = ((float4*)Ws)[(4 * k4 + 2) * 33 + l];
        float4 wv3 = ((float4*)Ws)[(4 * k4 + 3) * 33 + l];
#pragma unroll
        for (int i = 0; i < 4; i++) {
            float4 av = ((float4*)As)[(4 * w + i) * K4 + k4];
            acc[i][0] += av.x * wv0.x + av.y * wv1.x + av.z * wv2.x + av.w * wv3.x;
            acc[i][1] += av.x * wv0.y + av.y * wv1.y + av.z * wv2.y + av.w * wv3.y;
            acc[i][2] += av.x * wv0.z + av.y * wv1.z + av.z * wv2.z + av.w * wv3.z;
            acc[i][3] += av.x * wv0.w + av.y * wv1.w + av.z * wv2.w + av.w * wv3.w;
        }
    }
    float4 bv = ((const float4*)bias)[l];
#pragma unroll
    for (int i = 0; i < 4; i++) {
        int row = r0 + 4 * w + i;
        if (row < NN) {
            float4 o;
            o.x = acc[i][0] + bv.x;
            o.y = acc[i][1] + bv.y;
            o.z = acc[i][2] + bv.z;
            o.w = acc[i][3] + bv.w;
            ((float4*)outp)[row * 32 + l] = o;
        }
    }
}

// ---------------- edge pass A: E1e GEMM + e_new + e output ----------------
__global__ void k_edgeA(const float* __restrict__ e_in, const int* __restrict__ src,
                        const int* __restrict__ dst, const int* __restrict__ smask,
                        const float* __restrict__ bE1, float* __restrict__ e_out) {
    extern __shared__ float sm[];
    float* Ws = sm;             // 128 x stride132
    float* As = sm + 128 * 132; // 32 x 128

    const float* Gw = g_wt + 7 * DD * DD;  // W_E1 transposed
    for (int idx = threadIdx.x; idx < 4096; idx += 256) {
        int k = idx >> 5, j4 = idx & 31;
        ((float4*)Ws)[k * 33 + j4] = ((const float4*)Gw)[idx];
    }
    int e0 = blockIdx.x * 32;
    for (int idx = threadIdx.x; idx < 1024; idx += 256) {
        ((float4*)As)[idx] = ((const float4*)e_in)[e0 * 32 + idx];
    }
    __syncthreads();

    int w = threadIdx.x >> 5, l = threadIdx.x & 31;
    float acc[4][4] = {};
    for (int k4 = 0; k4 < 32; ++k4) {
        float4 wv0 = ((float4*)Ws)[(4 * k4 + 0) * 33 + l];
        float4 wv1 = ((float4*)Ws)[(4 * k4 + 1) * 33 + l];
        float4 wv2 = ((float4*)Ws)[(4 * k4 + 2) * 33 + l];
        float4 wv3 = ((float4*)Ws)[(4 * k4 + 3) * 33 + l];
#pragma unroll
        for (int i = 0; i < 4; i++) {
            float4 av = ((float4*)As)[(4 * w + i) * 32 + k4];
            acc[i][0] += av.x * wv0.x + av.y * wv1.x + av.z * wv2.x + av.w * wv3.x;
            acc[i][1] += av.x * wv0.y + av.y * wv1.y + av.z * wv2.y + av.w * wv3.y;
            acc[i][2] += av.x * wv0.z + av.y * wv1.z + av.z * wv2.z + av.w * wv3.z;
            acc[i][3] += av.x * wv0.w + av.y * wv1.w + av.z * wv2.w + av.w * wv3.w;
        }
    }
    float4 bv = ((const float4*)bE1)[l];
    const float4* P1 = (const float4*)g_proj[2];
    const float4* P2 = (const float4*)g_proj[3];
#pragma unroll
    for (int i = 0; i < 4; i++) {
        int eg = e0 + 4 * w + i;
        int s = src[eg], dd = dst[eg];
        float4 p1 = P1[dd * 32 + l];
        float4 p2 = P2[s * 32 + l];
        float4 en;
        en.x = 0.5f * (p1.x - p2.x + acc[i][0] + bv.x);
        en.y = 0.5f * (p1.y - p2.y + acc[i][1] + bv.y);
        en.z = 0.5f * (p1.z - p2.z + acc[i][2] + bv.z);
        en.w = 0.5f * (p1.w - p2.w + acc[i][3] + bv.w);
        float4 ev = ((float4*)As)[(4 * w + i) * 32 + l];
        float4 o;
        o.x = ev.x + lrelu(en.x);
        o.y = ev.y + lrelu(en.y);
        o.z = ev.z + lrelu(en.z);
        o.w = ev.w + lrelu(en.w);
        ((float4*)e_out)[(size_t)eg * 32 + l] = o;
        if (smask[eg]) ((float4*)g_enew)[(size_t)eg * 32 + l] = en;
    }
}

// ---------------- edge pass B: Vj GEMM on masked edges + fab accumulation ----------------
__global__ void k_edgeB(const float* __restrict__ h, const float* __restrict__ bV,
                        const int* __restrict__ src, const int* __restrict__ dst) {
    extern __shared__ float sm[];
    __shared__ int seid[32], ssrc[32], sdst[32];
    float* Ws = sm;
    float* As = sm + 128 * 132;

    int mc = g_mcount;
    int base = blockIdx.x * 32;
    if (base >= mc) return;
    int nt = min(32, mc - base);

    if (threadIdx.x < 32) {
        int eid = (threadIdx.x < nt) ? g_mlist[base + threadIdx.x] : -1;
        seid[threadIdx.x] = eid;
        ssrc[threadIdx.x] = (eid >= 0) ? src[eid] : 0;
        sdst[threadIdx.x] = (eid >= 0) ? dst[eid] : 0;
    }
    const float* Gw = g_wt + 8 * DD * DD;  // W_V transposed
    for (int idx = threadIdx.x; idx < 4096; idx += 256) {
        int k = idx >> 5, j4 = idx & 31;
        ((float4*)Ws)[k * 33 + j4] = ((const float4*)Gw)[idx];
    }
    __syncthreads();
    for (int idx = threadIdx.x; idx < 1024; idx += 256) {
        int e = idx >> 5, k4 = idx & 31;
        float4 a = make_float4(0.f, 0.f, 0.f, 0.f);
        if (e < nt) {
            float4 hs = ((const float4*)h)[ssrc[e] * 32 + k4];
            float4 hd = ((const float4*)h)[sdst[e] * 32 + k4];
            a.x = hs.x * hd.x; a.y = hs.y * hd.y; a.z = hs.z * hd.z; a.w = hs.w * hd.w;
        }
        ((float4*)As)[idx] = a;
    }
    __syncthreads();

    int w = threadIdx.x >> 5, l = threadIdx.x & 31;
    float acc[4][4] = {};
    for (int k4 = 0; k4 < 32; ++k4) {
        float4 wv0 = ((float4*)Ws)[(4 * k4 + 0) * 33 + l];
        float4 wv1 = ((float4*)Ws)[(4 * k4 + 1) * 33 + l];
        float4 wv2 = ((float4*)Ws)[(4 * k4 + 2) * 33 + l];
        float4 wv3 = ((float4*)Ws)[(4 * k4 + 3) * 33 + l];
#pragma unroll
        for (int i = 0; i < 4; i++) {
            float4 av = ((float4*)As)[(4 * w + i) * 32 + k4];
            acc[i][0] += av.x * wv0.x + av.y * wv1.x + av.z * wv2.x + av.w * wv3.x;
            acc[i][1] += av.x * wv0.y + av.y * wv1.y + av.z * wv2.y + av.w * wv3.y;
            acc[i][2] += av.x * wv0.z + av.y * wv1.z + av.z * wv2.z + av.w * wv3.z;
            acc[i][3] += av.x * wv0.w + av.y * wv1.w + av.z * wv2.w + av.w * wv3.w;
        }
    }
    float4 bv = ((const float4*)bV)[l];
#pragma unroll
    for (int i = 0; i < 4; i++) {
        int e = 4 * w + i;
        if (e >= nt) continue;  // uniform across warp
        float sv = relu_(acc[i][0] + bv.x) + relu_(acc[i][1] + bv.y) +
                   relu_(acc[i][2] + bv.z) + relu_(acc[i][3] + bv.w);
#pragma unroll
        for (int off = 16; off > 0; off >>= 1) sv += __shfl_xor_sync(0xffffffffu, sv, off);

        int eid = seid[e];
        float4 en = ((const float4*)g_enew)[(size_t)eid * 32 + l];
        float sq = en.x * en.x + en.y * en.y + en.z * en.z + en.w * en.w;
#pragma unroll
        for (int off = 16; off > 0; off >>= 1) sq += __shfl_xor_sync(0xffffffffu, sq, off);
        float L = sqrtf(sq);  // ||e_new||
        if (L > 1e-9f && sv > 0.f) {
            float r = 0.5f * sqrtf(L);
            float c = sv * expf(-r / 0.3f) / (1.2f * L * sqrtf(L));  // 4*sigma = 1.2
            float* fp = &g_facc[sdst[e] * DD + 4 * l];
            atomicAdd(fp + 0, c * en.x);
            atomicAdd(fp + 1, c * en.y);
            atomicAdd(fp + 2, c * en.z);
            atomicAdd(fp + 3, c * en.w);
        }
    }
}

// ---------------- node finalize ----------------
__global__ void k_final(const float* __restrict__ h, const float* __restrict__ p,
                        const float* __restrict__ dv, const float* __restrict__ dt,
                        float* __restrict__ out) {
    int w = threadIdx.x >> 5, l = threadIdx.x & 31;
    int n = blockIdx.x * 8 + w;
    int ix = n * 32 + l;
    const float4* V1 = (const float4*)g_proj[0];
    const float4* V2 = (const float4*)g_proj[1];
    const float4* P3 = (const float4*)g_proj[4];
    const float4* D1 = (const float4*)g_proj[5];
    const float4* D2 = (const float4*)g_proj[6];
    const float4* TH = (const float4*)g_proj[7];
    const float4* FA = (const float4*)g_facc;

    float4 v1 = V1[ix], v2 = V2[ix], p3 = P3[ix], d1 = D1[ix], d2 = D2[ix];
    float4 th = TH[ix], fa = FA[ix];
    float cnt = (float)g_cnt0[n];

    float4 f;
    f.x = (d1.x - v1.x) * (cnt * relu_(th.x)) + fa.x;
    f.y = (d1.y - v1.y) * (cnt * relu_(th.y)) + fa.y;
    f.z = (d1.z - v1.z) * (cnt * relu_(th.z)) + fa.z;
    f.w = (d1.w - v1.w) * (cnt * relu_(th.w)) + fa.w;

    float sq = f.x * f.x + f.y * f.y + f.z * f.z + f.w * f.w;
#pragma unroll
    for (int off = 16; off > 0; off >>= 1) sq += __shfl_xor_sync(0xffffffffu, sq, off);
    float inv = 1.f / (sqrtf(sq) + 1e-9f);

    float dtv = dt[n];
    float dtp = dtv + 0.5f * dtv * dtv;

    float4 hv = ((const float4*)h)[ix];
    float4 pv = ((const float4*)p)[ix];
    float4 dvv = ((const float4*)dv)[ix];

    float4 ho, po, dq;
    ho.x = hv.x + lrelu(v2.x + f.x * dtv);
    ho.y = hv.y + lrelu(v2.y + f.y * dtv);
    ho.z = hv.z + lrelu(v2.z + f.z * dtv);
    ho.w = hv.w + lrelu(v2.w + f.w * dtv);
    po.x = pv.x + lrelu(p3.x + f.x * dtp);
    po.y = pv.y + lrelu(p3.y + f.y * dtp);
    po.z = pv.z + lrelu(p3.z + f.z * dtp);
    po.w = pv.w + lrelu(p3.w + f.w * dtp);
    dq.x = dvv.x + lrelu(d2.x + f.x * inv);
    dq.y = dvv.y + lrelu(d2.y + f.y * inv);
    dq.z = dvv.z + lrelu(d2.z + f.z * inv);
    dq.w = dvv.w + lrelu(d2.w + f.w * inv);

    float4* outH = (float4*)out;
    float4* outP = (float4*)(out + (size_t)NN * DD + (size_t)EE * DD);
    float4* outD = (float4*)(out + 2 * (size_t)NN * DD + (size_t)EE * DD);
    outH[ix] = ho;
    outP[ix] = po;
    outD[ix] = dq;
}

// ---------------- launch ----------------
extern "C" void kernel_launch(void* const* d_in, const int* in_sizes, int n_in,
                              void* d_out, int out_size) {
    const float* h   = (const float*)d_in[0];
    const float* e   = (const float*)d_in[1];
    const float* p   = (const float*)d_in[2];
    const float* dv  = (const float*)d_in[3];
    const float* dt  = (const float*)d_in[4];
    const int* smask = (const int*)d_in[5];
    const int* src   = (const int*)d_in[6];
    const int* dst   = (const int*)d_in[7];
    const float* W_V1 = (const float*)d_in[8],  *b_V1 = (const float*)d_in[9];
    const float* W_V2 = (const float*)d_in[10], *b_V2 = (const float*)d_in[11];
    const float* W_E1 = (const float*)d_in[12], *b_E1 = (const float*)d_in[13];
    const float* W_P1 = (const float*)d_in[14], *b_P1 = (const float*)d_in[15];
    const float* W_P2 = (const float*)d_in[16], *b_P2 = (const float*)d_in[17];
    const float* W_P3 = (const float*)d_in[18], *b_P3 = (const float*)d_in[19];
    const float* W_D1 = (const float*)d_in[20], *b_D1 = (const float*)d_in[21];
    const float* W_D2 = (const float*)d_in[22], *b_D2 = (const float*)d_in[23];
    const float* W_V  = (const float*)d_in[24], *b_V  = (const float*)d_in[25];
    const float* W_T  = (const float*)d_in[26], *b_T  = (const float*)d_in[27];
    float* out = (float*)d_out;

    const int smemNode = 256 * 132 * 4 + 32 * 256 * 4;   // 167936 (pair 7 worst case)
    const int smemEdge = 128 * 132 * 4 + 32 * 128 * 4;   // 83968
    cudaFuncSetAttribute(k_nodegemm, cudaFuncAttributeMaxDynamicSharedMemorySize, smemNode);
    cudaFuncSetAttribute(k_edgeA,    cudaFuncAttributeMaxDynamicSharedMemorySize, smemEdge);
    cudaFuncSetAttribute(k_edgeB,    cudaFuncAttributeMaxDynamicSharedMemorySize, smemEdge);

    k_zero<<<640, 256>>>();
    k_wt<<<288, 256>>>(W_V1, W_V2, W_P1, W_P2, W_P3, W_D1, W_D2, W_E1, W_V, W_T);
    k_count<<<1250, 256>>>(smask, dst);
    k_nodegemm<<<dim3(313, 8), 256, smemNode>>>(h, p, dv, b_V1, b_V2, b_P1, b_P2, b_P3,
                                                b_D1, b_D2, b_T);
    k_edgeA<<<EE / 32, 256, smemEdge>>>(e, src, dst, smask, b_E1, out + (size_t)NN * DD);
    k_edgeB<<<EE / 32, 256, smemEdge>>>(h, b_V, src, dst);
    k_final<<<NN / 8, 256>>>(h, p, dv, dt, out);
}

// round 3
// speedup vs baseline: 1.0486x; 1.0486x over previous
#include <cuda_runtime.h>
#include <cuda_bf16.h>
#include <cstdint>
#include <math.h>

#define NN 10000
#define EE 320000
#define DD 128

// ================= static device scratch =================
__device__ float g_proj[8][NN * DD];          // V1h V2h P1h P2h P3h D1h D2h Th
__device__ float g_enew[(size_t)EE * DD];
__device__ float g_facc[NN * DD];
__device__ int   g_cnt0[NN];
__device__ int   g_mlist[EE];
__device__ int   g_mcount;
// pre-split weight tiles in the kernel's swizzled smem layout (32KB each):
// slots 0..6 node W (V1,V2,P1,P2,P3,D1,D2), 7 E1, 8 V, 9/10 = W_T halves
__device__ __align__(16) unsigned char g_wbh[11 * 32768];
__device__ __align__(16) unsigned char g_wbl[11 * 32768];

__device__ __forceinline__ float lrelu(float x) { return x > 0.f ? x : 0.01f * x; }
__device__ __forceinline__ float relu_(float x) { return x > 0.f ? x : 0.f; }

__device__ __forceinline__ uint32_t smem_u32(const void* p) {
    uint32_t a;
    asm("{ .reg .u64 t; cvta.to.shared.u64 t, %1; cvt.u32.u64 %0, t; }" : "=r"(a) : "l"(p));
    return a;
}
__device__ __forceinline__ uint32_t pack2(__nv_bfloat16 a, __nv_bfloat16 b) {
    __nv_bfloat162 t; t.x = a; t.y = b;
    return *reinterpret_cast<uint32_t*>(&t);
}

// swizzled byte offset inside a 128x128 bf16 tile: row stride 256B,
// 16B chunk index xor'ed with row&7  -> conflict-free ldmatrix
__device__ __forceinline__ uint32_t soff(int r, int c) {
    return (uint32_t)((r << 8) + ((((c >> 3) ^ (r & 7)) << 4) | ((c & 7) << 1)));
}

__device__ __forceinline__ void ldsm4(uint32_t* r, uint32_t addr) {
    asm volatile("ldmatrix.sync.aligned.m8n8.x4.shared.b16 {%0,%1,%2,%3}, [%4];"
                 : "=r"(r[0]), "=r"(r[1]), "=r"(r[2]), "=r"(r[3]) : "r"(addr));
}
__device__ __forceinline__ void mma16816(float& d0, float& d1, float& d2, float& d3,
                                         uint32_t a0, uint32_t a1, uint32_t a2, uint32_t a3,
                                         uint32_t b0, uint32_t b1) {
    asm volatile(
        "mma.sync.aligned.m16n8k16.row.col.f32.bf16.bf16.f32 "
        "{%0,%1,%2,%3}, {%4,%5,%6,%7}, {%8,%9}, {%0,%1,%2,%3};"
        : "+f"(d0), "+f"(d1), "+f"(d2), "+f"(d3)
        : "r"(a0), "r"(a1), "r"(a2), "r"(a3), "r"(b0), "r"(b1));
}

// split 8 fp32 -> hi/lo bf16x2 quads
__device__ __forceinline__ void cvt8(float4 v0, float4 v1, uint4& hi, uint4& lo) {
    __nv_bfloat16 a0 = __float2bfloat16(v0.x), a1 = __float2bfloat16(v0.y);
    __nv_bfloat16 a2 = __float2bfloat16(v0.z), a3 = __float2bfloat16(v0.w);
    __nv_bfloat16 a4 = __float2bfloat16(v1.x), a5 = __float2bfloat16(v1.y);
    __nv_bfloat16 a6 = __float2bfloat16(v1.z), a7 = __float2bfloat16(v1.w);
    hi.x = pack2(a0, a1); hi.y = pack2(a2, a3);
    hi.z = pack2(a4, a5); hi.w = pack2(a6, a7);
    lo.x = pack2(__float2bfloat16(v0.x - __bfloat162float(a0)),
                 __float2bfloat16(v0.y - __bfloat162float(a1)));
    lo.y = pack2(__float2bfloat16(v0.z - __bfloat162float(a2)),
                 __float2bfloat16(v0.w - __bfloat162float(a3)));
    lo.z = pack2(__float2bfloat16(v1.x - __bfloat162float(a4)),
                 __float2bfloat16(v1.y - __bfloat162float(a5)));
    lo.w = pack2(__float2bfloat16(v1.z - __bfloat162float(a6)),
                 __float2bfloat16(v1.w - __bfloat162float(a7)));
}

// shared memory layout
#define SM_BIAS 0
#define SM_ROWA 512     /* per-row src  */
#define SM_ROWB 1024    /* per-row dst  */
#define SM_ROWC 1536    /* per-row mask / eid */
#define SM_SV   2048    /* 128 row sums */
#define SM_AH   4096
#define SM_AL   (4096 + 32768)
#define SM_BH   (4096 + 65536)
#define SM_BL   (4096 + 98304)
#define SM_C    4096    /* fp32 C, stride 520B, overlays dead A (+1KB of BH) */
#define C_STRIDE 520
#define SM_TOTAL (4096 + 131072)

// 3-term split GEMM: acc[j] covers output cols j*8..j*8+7, rows wid*16 + (lane/4) and +8
__device__ __forceinline__ void gemm3(uint32_t smb, int lane, int wid, float (&acc)[16][4]) {
    const int fr = lane & 15;
    const int fc = (lane >> 4) << 3;
    const int m0 = wid * 16;
#pragma unroll
    for (int t = 0; t < 3; t++) {
        uint32_t abase = smb + (t == 2 ? SM_AL : SM_AH);
        uint32_t bbase = smb + (t == 1 ? SM_BL : SM_BH);
#pragma unroll
        for (int ks = 0; ks < 8; ks++) {
            uint32_t a[4];
            ldsm4(a, abase + soff(m0 + fr, ks * 16 + fc));
#pragma unroll
            for (int nn = 0; nn < 8; nn++) {
                uint32_t b[4];
                ldsm4(b, bbase + soff(nn * 16 + fr, ks * 16 + fc));
                mma16816(acc[2*nn][0], acc[2*nn][1], acc[2*nn][2], acc[2*nn][3],
                         a[0], a[1], a[2], a[3], b[0], b[2]);
                mma16816(acc[2*nn+1][0], acc[2*nn+1][1], acc[2*nn+1][2], acc[2*nn+1][3],
                         a[0], a[1], a[2], a[3], b[1], b[3]);
            }
        }
    }
}

__device__ __forceinline__ void store_C(char* sm, int lane, int wid, float (&acc)[16][4]) {
    int q = lane >> 2, m = lane & 3;
    int r0 = wid * 16 + q;
    char* base = sm + SM_C;
#pragma unroll
    for (int j = 0; j < 16; j++) {
        int col = j * 8 + m * 2;
        *(float2*)(base + r0 * C_STRIDE + col * 4) = make_float2(acc[j][0], acc[j][1]);
        *(float2*)(base + (r0 + 8) * C_STRIDE + col * 4) = make_float2(acc[j][2], acc[j][3]);
    }
}

__device__ __forceinline__ void copy_B(char* sm, int slot, int tid) {
    const uint4* gh = (const uint4*)(g_wbh + slot * 32768);
    const uint4* gl = (const uint4*)(g_wbl + slot * 32768);
    uint4* bh = (uint4*)(sm + SM_BH);
    uint4* bl = (uint4*)(sm + SM_BL);
    for (int i = tid; i < 2048; i += 256) { bh[i] = gh[i]; bl[i] = gl[i]; }
}

// ================= prep kernels =================
__global__ void k_zero() {
    int i = blockIdx.x * blockDim.x + threadIdx.x;
    int stride = gridDim.x * blockDim.x;
    for (int t = i; t < NN * DD; t += stride) g_facc[t] = 0.f;
    for (int t = i; t < NN; t += stride) g_cnt0[t] = 0;
    if (i == 0) g_mcount = 0;
}

__global__ void k_wbf(const float* W0, const float* W1, const float* W2, const float* W3,
                      const float* W4, const float* W5, const float* W6, const float* W7,
                      const float* W8, const float* WT) {
    const float* Wp[9] = {W0, W1, W2, W3, W4, W5, W6, W7, W8};
    int i = blockIdx.x * blockDim.x + threadIdx.x;
    int stride = gridDim.x * blockDim.x;
    for (int t = i; t < 11 * 16384; t += stride) {
        int slot = t >> 14, r = t & 16383;
        int n = r >> 7, k = r & 127;
        float w;
        if (slot < 9) w = Wp[slot][n * 128 + k];
        else if (slot == 9) w = WT[n * 256 + k];
        else w = WT[n * 256 + 128 + k];
        __nv_bfloat16 hi = __float2bfloat16(w);
        __nv_bfloat16 lo = __float2bfloat16(w - __bfloat162float(hi));
        uint32_t off = (uint32_t)slot * 32768u + soff(n, k);
        *reinterpret_cast<__nv_bfloat16*>(g_wbh + off) = hi;
        *reinterpret_cast<__nv_bfloat16*>(g_wbl + off) = lo;
    }
}

__global__ void k_count(const int* __restrict__ smask, const int* __restrict__ dst) {
    int e = blockIdx.x * 256 + threadIdx.x;
    int lane = threadIdx.x & 31;
    int sm_ = smask[e];
    int d_ = dst[e];
    unsigned bal = __ballot_sync(0xffffffffu, sm_ == 1);
    if (sm_ == 0) atomicAdd(&g_cnt0[d_], 1);
    int lead = bal ? (__ffs(bal) - 1) : 0;
    int basec = 0;
    if (bal && lane == lead) basec = atomicAdd(&g_mcount, __popc(bal));
    basec = __shfl_sync(0xffffffffu, basec, lead);
    if (sm_ == 1) g_mlist[basec + __popc(bal & ((1u << lane) - 1u))] = e;
}

// ================= node GEMMs (8 outputs) =================
__global__ void k_nodeg(const float* __restrict__ h, const float* __restrict__ p,
                        const float* __restrict__ dv,
                        const float* bV1, const float* bV2, const float* bP1,
                        const float* bP2, const float* bP3, const float* bD1,
                        const float* bD2, const float* bT) {
    extern __shared__ char sm[];
    uint32_t smb = smem_u32(sm);
    int tid = threadIdx.x, lane = tid & 31, wid = tid >> 5;
    int pair = blockIdx.y;
    int r0 = blockIdx.x * 128;

    const float* X0;
    const float* bias;
    int slot0;
    switch (pair) {
        case 0: X0 = h;  slot0 = 0; bias = bV1; break;
        case 1: X0 = h;  slot0 = 1; bias = bV2; break;
        case 2: X0 = p;  slot0 = 2; bias = bP1; break;
        case 3: X0 = p;  slot0 = 3; bias = bP2; break;
        case 4: X0 = p;  slot0 = 4; bias = bP3; break;
        case 5: X0 = dv; slot0 = 5; bias = bD1; break;
        case 6: X0 = dv; slot0 = 6; bias = bD2; break;
        default: X0 = h; slot0 = 9; bias = bT; break;
    }
    if (tid < 128) ((float*)(sm + SM_BIAS))[tid] = bias[tid];

    float acc[16][4];
#pragma unroll
    for (int j = 0; j < 16; j++)
#pragma unroll
        for (int i = 0; i < 4; i++) acc[j][i] = 0.f;

    int nph = (pair == 7) ? 2 : 1;
    for (int ph = 0; ph < nph; ph++) {
        const float* X = (pair == 7 && ph == 1) ? dv : X0;
        copy_B(sm, slot0 + ph, tid);
        for (int u = tid; u < 2048; u += 256) {
            int row = u >> 4, ch = u & 15;
            int g = r0 + row;
            float4 v0 = make_float4(0.f, 0.f, 0.f, 0.f), v1 = v0;
            if (g < NN) {
                v0 = ((const float4*)X)[(size_t)g * 32 + ch * 2];
                v1 = ((const float4*)X)[(size_t)g * 32 + ch * 2 + 1];
            }
            uint4 hi, lo; cvt8(v0, v1, hi, lo);
            uint32_t off = soff(row, ch * 8);
            *(uint4*)(sm + SM_AH + off) = hi;
            *(uint4*)(sm + SM_AL + off) = lo;
        }
        __syncthreads();
        gemm3(smb, lane, wid, acc);
        __syncthreads();
    }
    store_C(sm, lane, wid, acc);
    __syncthreads();

    float* outp = g_proj[pair];
    for (int u = tid; u < 4096; u += 256) {
        int row = u >> 5, c4 = u & 31;
        int g = r0 + row;
        if (g < NN) {
            float2 x = *(float2*)(sm + SM_C + row * C_STRIDE + c4 * 16);
            float2 y = *(float2*)(sm + SM_C + row * C_STRIDE + c4 * 16 + 8);
            float4 bv = *(float4*)(sm + SM_BIAS + c4 * 16);
            float4 o;
            o.x = x.x + bv.x; o.y = x.y + bv.y; o.z = y.x + bv.z; o.w = y.y + bv.w;
            ((float4*)outp)[(size_t)g * 32 + c4] = o;
        }
    }
}

// ================= edge pass A: E1e GEMM + e_new + e' output =================
__global__ void k_edgeA(const float* __restrict__ e_in, const int* __restrict__ src,
                        const int* __restrict__ dst, const int* __restrict__ smask,
                        const float* __restrict__ bE1, float* __restrict__ e_out) {
    extern __shared__ char sm[];
    uint32_t smb = smem_u32(sm);
    int tid = threadIdx.x, lane = tid & 31, wid = tid >> 5;
    int e0 = blockIdx.x * 128;

    if (tid < 128) {
        ((float*)(sm + SM_BIAS))[tid] = bE1[tid];
        int eg = e0 + tid;
        ((int*)(sm + SM_ROWA))[tid] = src[eg];
        ((int*)(sm + SM_ROWB))[tid] = dst[eg];
        ((int*)(sm + SM_ROWC))[tid] = smask[eg];
    }
    copy_B(sm, 7, tid);
    for (int u = tid; u < 2048; u += 256) {
        int row = u >> 4, ch = u & 15;
        float4 v0 = ((const float4*)e_in)[(size_t)(e0 + row) * 32 + ch * 2];
        float4 v1 = ((const float4*)e_in)[(size_t)(e0 + row) * 32 + ch * 2 + 1];
        uint4 hi, lo; cvt8(v0, v1, hi, lo);
        uint32_t off = soff(row, ch * 8);
        *(uint4*)(sm + SM_AH + off) = hi;
        *(uint4*)(sm + SM_AL + off) = lo;
    }
    __syncthreads();

    float acc[16][4];
#pragma unroll
    for (int j = 0; j < 16; j++)
#pragma unroll
        for (int i = 0; i < 4; i++) acc[j][i] = 0.f;
    gemm3(smb, lane, wid, acc);
    __syncthreads();
    store_C(sm, lane, wid, acc);
    __syncthreads();

    const int* ssrc = (const int*)(sm + SM_ROWA);
    const int* sdst = (const int*)(sm + SM_ROWB);
    const int* smsk = (const int*)(sm + SM_ROWC);
    const float4* P1 = (const float4*)g_proj[2];
    const float4* P2 = (const float4*)g_proj[3];
    for (int u = tid; u < 4096; u += 256) {
        int row = u >> 5, c4 = u & 31;
        int eg = e0 + row;
        int s = ssrc[row], dd = sdst[row], msk = smsk[row];
        float2 x = *(float2*)(sm + SM_C + row * C_STRIDE + c4 * 16);
        float2 y = *(float2*)(sm + SM_C + row * C_STRIDE + c4 * 16 + 8);
        float4 bv = *(float4*)(sm + SM_BIAS + c4 * 16);
        float4 p1 = P1[(size_t)dd * 32 + c4];
        float4 p2 = P2[(size_t)s * 32 + c4];
        float4 ev = ((const float4*)e_in)[(size_t)eg * 32 + c4];
        float4 en;
        en.x = 0.5f * (p1.x - p2.x + x.x + bv.x);
        en.y = 0.5f * (p1.y - p2.y + x.y + bv.y);
        en.z = 0.5f * (p1.z - p2.z + y.x + bv.z);
        en.w = 0.5f * (p1.w - p2.w + y.y + bv.w);
        float4 o;
        o.x = ev.x + lrelu(en.x);
        o.y = ev.y + lrelu(en.y);
        o.z = ev.z + lrelu(en.z);
        o.w = ev.w + lrelu(en.w);
        ((float4*)e_out)[(size_t)eg * 32 + c4] = o;
        if (msk) ((float4*)g_enew)[(size_t)eg * 32 + c4] = en;
    }
}

// ================= edge pass B: masked V GEMM + fab atomics =================
__global__ void k_edgeB(const float* __restrict__ h, const float* __restrict__ bV,
                        const int* __restrict__ src, const int* __restrict__ dst) {
    extern __shared__ char sm[];
    uint32_t smb = smem_u32(sm);
    int tid = threadIdx.x, lane = tid & 31, wid = tid >> 5;
    int mc = g_mcount;
    int base = blockIdx.x * 128;
    if (base >= mc) return;
    int nt = min(128, mc - base);

    int* seid = (int*)(sm + SM_ROWC);
    int* ssrc = (int*)(sm + SM_ROWA);
    int* sdst = (int*)(sm + SM_ROWB);
    if (tid < 128) {
        ((float*)(sm + SM_BIAS))[tid] = bV[tid];
        int eid = (tid < nt) ? g_mlist[base + tid] : -1;
        seid[tid] = eid;
        ssrc[tid] = (eid >= 0) ? src[eid] : 0;
        sdst[tid] = (eid >= 0) ? dst[eid] : 0;
    }
    copy_B(sm, 8, tid);
    __syncthreads();
    for (int u = tid; u < 2048; u += 256) {
        int row = u >> 4, ch = u & 15;
        float4 v0 = make_float4(0.f, 0.f, 0.f, 0.f), v1 = v0;
        if (row < nt) {
            float4 hs0 = ((const float4*)h)[(size_t)ssrc[row] * 32 + ch * 2];
            float4 hs1 = ((const float4*)h)[(size_t)ssrc[row] * 32 + ch * 2 + 1];
            float4 hd0 = ((const float4*)h)[(size_t)sdst[row] * 32 + ch * 2];
            float4 hd1 = ((const float4*)h)[(size_t)sdst[row] * 32 + ch * 2 + 1];
            v0.x = hs0.x * hd0.x; v0.y = hs0.y * hd0.y;
            v0.z = hs0.z * hd0.z; v0.w = hs0.w * hd0.w;
            v1.x = hs1.x * hd1.x; v1.y = hs1.y * hd1.y;
            v1.z = hs1.z * hd1.z; v1.w = hs1.w * hd1.w;
        }
        uint4 hi, lo; cvt8(v0, v1, hi, lo);
        uint32_t off = soff(row, ch * 8);
        *(uint4*)(sm + SM_AH + off) = hi;
        *(uint4*)(sm + SM_AL + off) = lo;
    }
    __syncthreads();

    float acc[16][4];
#pragma unroll
    for (int j = 0; j < 16; j++)
#pragma unroll
        for (int i = 0; i < 4; i++) acc[j][i] = 0.f;
    gemm3(smb, lane, wid, acc);

    // register row-sums of relu(acc + bias): rows wid*16 + q and +8
    const float* bias_s = (const float*)(sm + SM_BIAS);
    int q = lane >> 2, m = lane & 3;
    float s0 = 0.f, s1 = 0.f;
#pragma unroll
    for (int j = 0; j < 16; j++) {
        float b0 = bias_s[j * 8 + m * 2], b1 = bias_s[j * 8 + m * 2 + 1];
        s0 += relu_(acc[j][0] + b0) + relu_(acc[j][1] + b1);
        s1 += relu_(acc[j][2] + b0) + relu_(acc[j][3] + b1);
    }
    s0 += __shfl_xor_sync(0xffffffffu, s0, 1);
    s0 += __shfl_xor_sync(0xffffffffu, s0, 2);
    s1 += __shfl_xor_sync(0xffffffffu, s1, 1);
    s1 += __shfl_xor_sync(0xffffffffu, s1, 2);
    float* svb = (float*)(sm + SM_SV);
    if (m == 0) {
        svb[wid * 16 + q] = s0;
        svb[wid * 16 + q + 8] = s1;
    }
    __syncthreads();

    if (tid < nt) {
        float sv = svb[tid];
        int eid = seid[tid];
        const float4* EN = (const float4*)g_enew + (size_t)eid * 32;
        float sq = 0.f;
#pragma unroll 8
        for (int k4 = 0; k4 < 32; k4++) {
            float4 en = EN[k4];
            sq += en.x * en.x + en.y * en.y + en.z * en.z + en.w * en.w;
        }
        float L = sqrtf(sq);
        if (L > 1e-9f && sv > 0.f) {
            float r = 0.5f * sqrtf(L);
            float cf = sv * expf(-r / 0.3f) / (1.2f * L * sqrtf(L));
            float* fp = &g_facc[(size_t)sdst[tid] * DD];
#pragma unroll 8
            for (int k4 = 0; k4 < 32; k4++) {
                float4 en = EN[k4];
                atomicAdd(fp + k4 * 4 + 0, cf * en.x);
                atomicAdd(fp + k4 * 4 + 1, cf * en.y);
                atomicAdd(fp + k4 * 4 + 2, cf * en.z);
                atomicAdd(fp + k4 * 4 + 3, cf * en.w);
            }
        }
    }
}

// ================= node finalize =================
__global__ void k_final(const float* __restrict__ h, const float* __restrict__ p,
                        const float* __restrict__ dv, const float* __restrict__ dt,
                        float* __restrict__ out) {
    int w = threadIdx.x >> 5, l = threadIdx.x & 31;
    int n = blockIdx.x * 8 + w;
    int ix = n * 32 + l;
    const float4* V1 = (const float4*)g_proj[0];
    const float4* V2 = (const float4*)g_proj[1];
    const float4* P3 = (const float4*)g_proj[4];
    const float4* D1 = (const float4*)g_proj[5];
    const float4* D2 = (const float4*)g_proj[6];
    const float4* TH = (const float4*)g_proj[7];
    const float4* FA = (const float4*)g_facc;

    float4 v1 = V1[ix], v2 = V2[ix], p3 = P3[ix], d1 = D1[ix], d2 = D2[ix];
    float4 th = TH[ix], fa = FA[ix];
    float cnt = (float)g_cnt0[n];

    float4 f;
    f.x = (d1.x - v1.x) * (cnt * relu_(th.x)) + fa.x;
    f.y = (d1.y - v1.y) * (cnt * relu_(th.y)) + fa.y;
    f.z = (d1.z - v1.z) * (cnt * relu_(th.z)) + fa.z;
    f.w = (d1.w - v1.w) * (cnt * relu_(th.w)) + fa.w;

    float sq = f.x * f.x + f.y * f.y + f.z * f.z + f.w * f.w;
#pragma unroll
    for (int off = 16; off > 0; off >>= 1) sq += __shfl_xor_sync(0xffffffffu, sq, off);
    float inv = 1.f / (sqrtf(sq) + 1e-9f);

    float dtv = dt[n];
    float dtp = dtv + 0.5f * dtv * dtv;

    float4 hv = ((const float4*)h)[ix];
    float4 pv = ((const float4*)p)[ix];
    float4 dvv = ((const float4*)dv)[ix];

    float4 ho, po, dq;
    ho.x = hv.x + lrelu(v2.x + f.x * dtv);
    ho.y = hv.y + lrelu(v2.y + f.y * dtv);
    ho.z = hv.z + lrelu(v2.z + f.z * dtv);
    ho.w = hv.w + lrelu(v2.w + f.w * dtv);
    po.x = pv.x + lrelu(p3.x + f.x * dtp);
    po.y = pv.y + lrelu(p3.y + f.y * dtp);
    po.z = pv.z + lrelu(p3.z + f.z * dtp);
    po.w = pv.w + lrelu(p3.w + f.w * dtp);
    dq.x = dvv.x + lrelu(d2.x + f.x * inv);
    dq.y = dvv.y + lrelu(d2.y + f.y * inv);
    dq.z = dvv.z + lrelu(d2.z + f.z * inv);
    dq.w = dvv.w + lrelu(d2.w + f.w * inv);

    float4* outH = (float4*)out;
    float4* outP = (float4*)(out + (size_t)NN * DD + (size_t)EE * DD);
    float4* outD = (float4*)(out + 2 * (size_t)NN * DD + (size_t)EE * DD);
    outH[ix] = ho;
    outP[ix] = po;
    outD[ix] = dq;
}

// ================= launch =================
extern "C" void kernel_launch(void* const* d_in, const int* in_sizes, int n_in,
                              void* d_out, int out_size) {
    const float* h   = (const float*)d_in[0];
    const float* e   = (const float*)d_in[1];
    const float* p   = (const float*)d_in[2];
    const float* dv  = (const float*)d_in[3];
    const float* dt  = (const float*)d_in[4];
    const int* smask = (const int*)d_in[5];
    const int* src   = (const int*)d_in[6];
    const int* dst   = (const int*)d_in[7];
    const float* W_V1 = (const float*)d_in[8],  *b_V1 = (const float*)d_in[9];
    const float* W_V2 = (const float*)d_in[10], *b_V2 = (const float*)d_in[11];
    const float* W_E1 = (const float*)d_in[12], *b_E1 = (const float*)d_in[13];
    const float* W_P1 = (const float*)d_in[14], *b_P1 = (const float*)d_in[15];
    const float* W_P2 = (const float*)d_in[16], *b_P2 = (const float*)d_in[17];
    const float* W_P3 = (const float*)d_in[18], *b_P3 = (const float*)d_in[19];
    const float* W_D1 = (const float*)d_in[20], *b_D1 = (const float*)d_in[21];
    const float* W_D2 = (const float*)d_in[22], *b_D2 = (const float*)d_in[23];
    const float* W_V  = (const float*)d_in[24], *b_V  = (const float*)d_in[25];
    const float* W_T  = (const float*)d_in[26], *b_T  = (const float*)d_in[27];
    float* out = (float*)d_out;

    cudaFuncSetAttribute(k_nodeg, cudaFuncAttributeMaxDynamicSharedMemorySize, SM_TOTAL);
    cudaFuncSetAttribute(k_edgeA, cudaFuncAttributeMaxDynamicSharedMemorySize, SM_TOTAL);
    cudaFuncSetAttribute(k_edgeB, cudaFuncAttributeMaxDynamicSharedMemorySize, SM_TOTAL);

    k_zero<<<640, 256>>>();
    k_wbf<<<704, 256>>>(W_V1, W_V2, W_P1, W_P2, W_P3, W_D1, W_D2, W_E1, W_V, W_T);
    k_count<<<EE / 256, 256>>>(smask, dst);
    k_nodeg<<<dim3((NN + 127) / 128, 8), 256, SM_TOTAL>>>(h, p, dv, b_V1, b_V2, b_P1,
                                                          b_P2, b_P3, b_D1, b_D2, b_T);
    k_edgeA<<<EE / 128, 256, SM_TOTAL>>>(e, src, dst, smask, b_E1, out + (size_t)NN * DD);
    k_edgeB<<<EE / 128, 256, SM_TOTAL>>>(h, b_V, src, dst);
    k_final<<<NN / 8, 256>>>(h, p, dv, dt, out);
}

// round 4
// speedup vs baseline: 1.7573x; 1.6759x over previous
#include <cuda_runtime.h>
#include <cuda_bf16.h>
#include <cstdint>
#include <math.h>

#define NN 10000
#define EE 320000
#define DD 128

// ================= static device scratch =================
__device__ float g_proj[8][NN * DD];          // V1h V2h P1h P2h P3h D1h D2h Th
__device__ float g_enew[(size_t)EE * DD];
__device__ float g_facc[NN * DD];
__device__ int   g_cnt0[NN];
__device__ int   g_mlist[EE];
__device__ int   g_mcount;
// pre-split weight tiles in swizzled layout (32KB each):
// slots 0..6 node W (V1,V2,P1,P2,P3,D1,D2), 7 E1, 8 V, 9/10 = W_T halves
__device__ __align__(16) unsigned char g_wbh[11 * 32768];
__device__ __align__(16) unsigned char g_wbl[11 * 32768];

__device__ __forceinline__ float lrelu(float x) { return x > 0.f ? x : 0.01f * x; }
__device__ __forceinline__ float relu_(float x) { return x > 0.f ? x : 0.f; }

__device__ __forceinline__ uint32_t smem_u32(const void* p) {
    uint32_t a;
    asm("{ .reg .u64 t; cvta.to.shared.u64 t, %1; cvt.u32.u64 %0, t; }" : "=r"(a) : "l"(p));
    return a;
}
__device__ __forceinline__ uint32_t pack2(__nv_bfloat16 a, __nv_bfloat16 b) {
    __nv_bfloat162 t; t.x = a; t.y = b;
    return *reinterpret_cast<uint32_t*>(&t);
}

// swizzled byte offset inside a 128x128 bf16 tile: row stride 256B,
// 16B chunk index xor'ed with row&7  -> conflict-free ldmatrix
__device__ __forceinline__ uint32_t soff(int r, int c) {
    return (uint32_t)((r << 8) + ((((c >> 3) ^ (r & 7)) << 4) | ((c & 7) << 1)));
}

__device__ __forceinline__ void ldsm4(uint32_t* r, uint32_t addr) {
    asm volatile("ldmatrix.sync.aligned.m8n8.x4.shared.b16 {%0,%1,%2,%3}, [%4];"
                 : "=r"(r[0]), "=r"(r[1]), "=r"(r[2]), "=r"(r[3]) : "r"(addr));
}
__device__ __forceinline__ void mma16816(float* d,
                                         const uint32_t* a,
                                         uint32_t b0, uint32_t b1) {
    asm volatile(
        "mma.sync.aligned.m16n8k16.row.col.f32.bf16.bf16.f32 "
        "{%0,%1,%2,%3}, {%4,%5,%6,%7}, {%8,%9}, {%0,%1,%2,%3};"
        : "+f"(d[0]), "+f"(d[1]), "+f"(d[2]), "+f"(d[3])
        : "r"(a[0]), "r"(a[1]), "r"(a[2]), "r"(a[3]), "r"(b0), "r"(b1));
}

// split 8 fp32 -> hi/lo bf16x2 quads
__device__ __forceinline__ void cvt8(float4 v0, float4 v1, uint4& hi, uint4& lo) {
    __nv_bfloat16 a0 = __float2bfloat16(v0.x), a1 = __float2bfloat16(v0.y);
    __nv_bfloat16 a2 = __float2bfloat16(v0.z), a3 = __float2bfloat16(v0.w);
    __nv_bfloat16 a4 = __float2bfloat16(v1.x), a5 = __float2bfloat16(v1.y);
    __nv_bfloat16 a6 = __float2bfloat16(v1.z), a7 = __float2bfloat16(v1.w);
    hi.x = pack2(a0, a1); hi.y = pack2(a2, a3);
    hi.z = pack2(a4, a5); hi.w = pack2(a6, a7);
    lo.x = pack2(__float2bfloat16(v0.x - __bfloat162float(a0)),
                 __float2bfloat16(v0.y - __bfloat162float(a1)));
    lo.y = pack2(__float2bfloat16(v0.z - __bfloat162float(a2)),
                 __float2bfloat16(v0.w - __bfloat162float(a3)));
    lo.z = pack2(__float2bfloat16(v1.x - __bfloat162float(a4)),
                 __float2bfloat16(v1.y - __bfloat162float(a5)));
    lo.w = pack2(__float2bfloat16(v1.z - __bfloat162float(a6)),
                 __float2bfloat16(v1.w - __bfloat162float(a7)));
}

// shared memory layout
#define SM_BIAS 0
#define SM_ROWA 512     /* per-row src  */
#define SM_ROWB 1024    /* per-row dst  */
#define SM_ROWC 1536    /* per-row mask / eid */
#define SM_SV   2048    /* 2 x 128 partial row sums */
#define SM_AH   4096
#define SM_AL   (4096 + 32768)
#define SM_BH   (4096 + 65536)
#define SM_BL   (4096 + 98304)
#define SM_C    4096    /* fp32 C, stride 520B, overlays dead A + 1KB of BH */
#define C_STRIDE 520
#define SM_TOTAL (4096 + 131072)

// ---- 3-term split GEMM, warp tile 16(M) x 64(N), 16 warps ----
// warp wm = wid&7 (M block), wn = wid>>3 (N half)
// acc[2*bn+p][*]: cols wn*64 + bn*16 + p*8 .. +7, rows wm*16 + (lane>>2) and +8
__device__ __forceinline__ void gemm3(uint32_t smb, int lane, int wm, int wn,
                                      float (&acc)[8][4]) {
    const int fr = lane & 15;
    const int fc = (lane >> 4) << 3;
    const int m0 = wm * 16;
    const int n0 = wn * 64;
#pragma unroll
    for (int ks = 0; ks < 8; ks++) {
        uint32_t aH[4], aL[4];
        ldsm4(aH, smb + SM_AH + soff(m0 + fr, ks * 16 + fc));
        ldsm4(aL, smb + SM_AL + soff(m0 + fr, ks * 16 + fc));
#pragma unroll
        for (int bn = 0; bn < 4; bn++) {
            uint32_t bH[4], bL[4];
            ldsm4(bH, smb + SM_BH + soff(n0 + bn * 16 + fr, ks * 16 + fc));
            ldsm4(bL, smb + SM_BL + soff(n0 + bn * 16 + fr, ks * 16 + fc));
            mma16816(acc[2 * bn],     aH, bH[0], bH[2]);
            mma16816(acc[2 * bn + 1], aH, bH[1], bH[3]);
            mma16816(acc[2 * bn],     aL, bH[0], bH[2]);
            mma16816(acc[2 * bn + 1], aL, bH[1], bH[3]);
            mma16816(acc[2 * bn],     aH, bL[0], bL[2]);
            mma16816(acc[2 * bn + 1], aH, bL[1], bL[3]);
        }
    }
}

__device__ __forceinline__ void store_C(char* sm, int lane, int wm, int wn,
                                        float (&acc)[8][4]) {
    int q = lane >> 2, m = lane & 3;
    int r0 = wm * 16 + q;
    char* base = sm + SM_C;
#pragma unroll
    for (int j = 0; j < 8; j++) {
        int col = wn * 64 + j * 8 + m * 2;
        *(float2*)(base + r0 * C_STRIDE + col * 4) = make_float2(acc[j][0], acc[j][1]);
        *(float2*)(base + (r0 + 8) * C_STRIDE + col * 4) = make_float2(acc[j][2], acc[j][3]);
    }
}

__device__ __forceinline__ void copy_B(char* sm, int slot, int tid) {
    const uint4* gh = (const uint4*)(g_wbh + slot * 32768);
    const uint4* gl = (const uint4*)(g_wbl + slot * 32768);
    uint4* bh = (uint4*)(sm + SM_BH);
    uint4* bl = (uint4*)(sm + SM_BL);
    for (int i = tid; i < 2048; i += 512) { bh[i] = gh[i]; bl[i] = gl[i]; }
}

// ================= prep kernels =================
__global__ void k_zero() {
    int i = blockIdx.x * blockDim.x + threadIdx.x;
    int stride = gridDim.x * blockDim.x;
    for (int t = i; t < NN * DD; t += stride) g_facc[t] = 0.f;
    for (int t = i; t < NN; t += stride) g_cnt0[t] = 0;
    if (i == 0) g_mcount = 0;
}

__global__ void k_wbf(const float* W0, const float* W1, const float* W2, const float* W3,
                      const float* W4, const float* W5, const float* W6, const float* W7,
                      const float* W8, const float* WT) {
    const float* Wp[9] = {W0, W1, W2, W3, W4, W5, W6, W7, W8};
    int i = blockIdx.x * blockDim.x + threadIdx.x;
    int stride = gridDim.x * blockDim.x;
    for (int t = i; t < 11 * 16384; t += stride) {
        int slot = t >> 14, r = t & 16383;
        int n = r >> 7, k = r & 127;
        float w;
        if (slot < 9) w = Wp[slot][n * 128 + k];
        else if (slot == 9) w = WT[n * 256 + k];
        else w = WT[n * 256 + 128 + k];
        __nv_bfloat16 hi = __float2bfloat16(w);
        __nv_bfloat16 lo = __float2bfloat16(w - __bfloat162float(hi));
        uint32_t off = (uint32_t)slot * 32768u + soff(n, k);
        *reinterpret_cast<__nv_bfloat16*>(g_wbh + off) = hi;
        *reinterpret_cast<__nv_bfloat16*>(g_wbl + off) = lo;
    }
}

__global__ void k_count(const int* __restrict__ smask, const int* __restrict__ dst) {
    int e = blockIdx.x * 256 + threadIdx.x;
    int lane = threadIdx.x & 31;
    int sm_ = smask[e];
    int d_ = dst[e];
    unsigned bal = __ballot_sync(0xffffffffu, sm_ == 1);
    if (sm_ == 0) atomicAdd(&g_cnt0[d_], 1);
    int lead = bal ? (__ffs(bal) - 1) : 0;
    int basec = 0;
    if (bal && lane == lead) basec = atomicAdd(&g_mcount, __popc(bal));
    basec = __shfl_sync(0xffffffffu, basec, lead);
    if (sm_ == 1) g_mlist[basec + __popc(bal & ((1u << lane) - 1u))] = e;
}

// ================= node GEMMs (8 outputs) =================
__global__ void __launch_bounds__(512, 1)
k_nodeg(const float* __restrict__ h, const float* __restrict__ p,
        const float* __restrict__ dv,
        const float* bV1, const float* bV2, const float* bP1,
        const float* bP2, const float* bP3, const float* bD1,
        const float* bD2, const float* bT) {
    extern __shared__ char sm[];
    uint32_t smb = smem_u32(sm);
    int tid = threadIdx.x, lane = tid & 31, wid = tid >> 5;
    int wm = wid & 7, wn = wid >> 3;
    int pair = blockIdx.y;
    int r0 = blockIdx.x * 128;

    const float* X0;
    const float* bias;
    int slot0;
    switch (pair) {
        case 0: X0 = h;  slot0 = 0; bias = bV1; break;
        case 1: X0 = h;  slot0 = 1; bias = bV2; break;
        case 2: X0 = p;  slot0 = 2; bias = bP1; break;
        case 3: X0 = p;  slot0 = 3; bias = bP2; break;
        case 4: X0 = p;  slot0 = 4; bias = bP3; break;
        case 5: X0 = dv; slot0 = 5; bias = bD1; break;
        case 6: X0 = dv; slot0 = 6; bias = bD2; break;
        default: X0 = h; slot0 = 9; bias = bT; break;
    }
    if (tid < 128) ((float*)(sm + SM_BIAS))[tid] = bias[tid];

    float acc[8][4];
#pragma unroll
    for (int j = 0; j < 8; j++)
#pragma unroll
        for (int i = 0; i < 4; i++) acc[j][i] = 0.f;

    int nph = (pair == 7) ? 2 : 1;
    for (int ph = 0; ph < nph; ph++) {
        const float* X = (pair == 7 && ph == 1) ? dv : X0;
        copy_B(sm, slot0 + ph, tid);
        for (int u = tid; u < 2048; u += 512) {
            int row = u >> 4, ch = u & 15;
            int g = r0 + row;
            float4 v0 = make_float4(0.f, 0.f, 0.f, 0.f), v1 = v0;
            if (g < NN) {
                v0 = ((const float4*)X)[(size_t)g * 32 + ch * 2];
                v1 = ((const float4*)X)[(size_t)g * 32 + ch * 2 + 1];
            }
            uint4 hi, lo; cvt8(v0, v1, hi, lo);
            uint32_t off = soff(row, ch * 8);
            *(uint4*)(sm + SM_AH + off) = hi;
            *(uint4*)(sm + SM_AL + off) = lo;
        }
        __syncthreads();
        gemm3(smb, lane, wm, wn, acc);
        __syncthreads();
    }
    store_C(sm, lane, wm, wn, acc);
    __syncthreads();

    float* outp = g_proj[pair];
    for (int u = tid; u < 4096; u += 512) {
        int row = u >> 5, c4 = u & 31;
        int g = r0 + row;
        if (g < NN) {
            float2 x = *(float2*)(sm + SM_C + row * C_STRIDE + c4 * 16);
            float2 y = *(float2*)(sm + SM_C + row * C_STRIDE + c4 * 16 + 8);
            float4 bv = *(float4*)(sm + SM_BIAS + c4 * 16);
            float4 o;
            o.x = x.x + bv.x; o.y = x.y + bv.y; o.z = y.x + bv.z; o.w = y.y + bv.w;
            ((float4*)outp)[(size_t)g * 32 + c4] = o;
        }
    }
}

// ================= edge pass A: E1e GEMM + e_new + e' output =================
__global__ void __launch_bounds__(512, 1)
k_edgeA(const float* __restrict__ e_in, const int* __restrict__ src,
        const int* __restrict__ dst, const int* __restrict__ smask,
        const float* __restrict__ bE1, float* __restrict__ e_out) {
    extern __shared__ char sm[];
    uint32_t smb = smem_u32(sm);
    int tid = threadIdx.x, lane = tid & 31, wid = tid >> 5;
    int wm = wid & 7, wn = wid >> 3;
    int e0 = blockIdx.x * 128;

    if (tid < 128) {
        ((float*)(sm + SM_BIAS))[tid] = bE1[tid];
        int eg = e0 + tid;
        ((int*)(sm + SM_ROWA))[tid] = src[eg];
        ((int*)(sm + SM_ROWB))[tid] = dst[eg];
        ((int*)(sm + SM_ROWC))[tid] = smask[eg];
    }
    copy_B(sm, 7, tid);
    for (int u = tid; u < 2048; u += 512) {
        int row = u >> 4, ch = u & 15;
        float4 v0 = ((const float4*)e_in)[(size_t)(e0 + row) * 32 + ch * 2];
        float4 v1 = ((const float4*)e_in)[(size_t)(e0 + row) * 32 + ch * 2 + 1];
        uint4 hi, lo; cvt8(v0, v1, hi, lo);
        uint32_t off = soff(row, ch * 8);
        *(uint4*)(sm + SM_AH + off) = hi;
        *(uint4*)(sm + SM_AL + off) = lo;
    }
    __syncthreads();

    float acc[8][4];
#pragma unroll
    for (int j = 0; j < 8; j++)
#pragma unroll
        for (int i = 0; i < 4; i++) acc[j][i] = 0.f;
    gemm3(smb, lane, wm, wn, acc);
    __syncthreads();
    store_C(sm, lane, wm, wn, acc);
    __syncthreads();

    const int* ssrc = (const int*)(sm + SM_ROWA);
    const int* sdst = (const int*)(sm + SM_ROWB);
    const int* smsk = (const int*)(sm + SM_ROWC);
    const float4* P1 = (const float4*)g_proj[2];
    const float4* P2 = (const float4*)g_proj[3];
    for (int u = tid; u < 4096; u += 512) {
        int row = u >> 5, c4 = u & 31;
        int eg = e0 + row;
        int s = ssrc[row], dd = sdst[row], msk = smsk[row];
        float2 x = *(float2*)(sm + SM_C + row * C_STRIDE + c4 * 16);
        float2 y = *(float2*)(sm + SM_C + row * C_STRIDE + c4 * 16 + 8);
        float4 bv = *(float4*)(sm + SM_BIAS + c4 * 16);
        float4 p1 = P1[(size_t)dd * 32 + c4];
        float4 p2 = P2[(size_t)s * 32 + c4];
        float4 ev = ((const float4*)e_in)[(size_t)eg * 32 + c4];
        float4 en;
        en.x = 0.5f * (p1.x - p2.x + x.x + bv.x);
        en.y = 0.5f * (p1.y - p2.y + x.y + bv.y);
        en.z = 0.5f * (p1.z - p2.z + y.x + bv.z);
        en.w = 0.5f * (p1.w - p2.w + y.y + bv.w);
        float4 o;
        o.x = ev.x + lrelu(en.x);
        o.y = ev.y + lrelu(en.y);
        o.z = ev.z + lrelu(en.z);
        o.w = ev.w + lrelu(en.w);
        ((float4*)e_out)[(size_t)eg * 32 + c4] = o;
        if (msk) ((float4*)g_enew)[(size_t)eg * 32 + c4] = en;
    }
}

// ================= edge pass B: masked V GEMM + fab atomics =================
__global__ void __launch_bounds__(512, 1)
k_edgeB(const float* __restrict__ h, const float* __restrict__ bV,
        const int* __restrict__ src, const int* __restrict__ dst) {
    extern __shared__ char sm[];
    uint32_t smb = smem_u32(sm);
    int tid = threadIdx.x, lane = tid & 31, wid = tid >> 5;
    int wm = wid & 7, wn = wid >> 3;
    int mc = g_mcount;
    int base = blockIdx.x * 128;
    if (base >= mc) return;
    int nt = min(128, mc - base);

    int* seid = (int*)(sm + SM_ROWC);
    int* ssrc = (int*)(sm + SM_ROWA);
    int* sdst = (int*)(sm + SM_ROWB);
    if (tid < 128) {
        ((float*)(sm + SM_BIAS))[tid] = bV[tid];
        int eid = (tid < nt) ? g_mlist[base + tid] : -1;
        seid[tid] = eid;
        ssrc[tid] = (eid >= 0) ? src[eid] : 0;
        sdst[tid] = (eid >= 0) ? dst[eid] : 0;
    }
    copy_B(sm, 8, tid);
    __syncthreads();
    for (int u = tid; u < 2048; u += 512) {
        int row = u >> 4, ch = u & 15;
        float4 v0 = make_float4(0.f, 0.f, 0.f, 0.f), v1 = v0;
        if (row < nt) {
            float4 hs0 = ((const float4*)h)[(size_t)ssrc[row] * 32 + ch * 2];
            float4 hs1 = ((const float4*)h)[(size_t)ssrc[row] * 32 + ch * 2 + 1];
            float4 hd0 = ((const float4*)h)[(size_t)sdst[row] * 32 + ch * 2];
            float4 hd1 = ((const float4*)h)[(size_t)sdst[row] * 32 + ch * 2 + 1];
            v0.x = hs0.x * hd0.x; v0.y = hs0.y * hd0.y;
            v0.z = hs0.z * hd0.z; v0.w = hs0.w * hd0.w;
            v1.x = hs1.x * hd1.x; v1.y = hs1.y * hd1.y;
            v1.z = hs1.z * hd1.z; v1.w = hs1.w * hd1.w;
        }
        uint4 hi, lo; cvt8(v0, v1, hi, lo);
        uint32_t off = soff(row, ch * 8);
        *(uint4*)(sm + SM_AH + off) = hi;
        *(uint4*)(sm + SM_AL + off) = lo;
    }
    __syncthreads();

    float acc[8][4];
#pragma unroll
    for (int j = 0; j < 8; j++)
#pragma unroll
        for (int i = 0; i < 4; i++) acc[j][i] = 0.f;
    gemm3(smb, lane, wm, wn, acc);

    // partial row-sums of relu(acc + bias): this warp covers cols wn*64..+63
    const float* bias_s = (const float*)(sm + SM_BIAS);
    int q = lane >> 2, m = lane & 3;
    float s0 = 0.f, s1 = 0.f;
#pragma unroll
    for (int j = 0; j < 8; j++) {
        float b0 = bias_s[wn * 64 + j * 8 + m * 2];
        float b1 = bias_s[wn * 64 + j * 8 + m * 2 + 1];
        s0 += relu_(acc[j][0] + b0) + relu_(acc[j][1] + b1);
        s1 += relu_(acc[j][2] + b0) + relu_(acc[j][3] + b1);
    }
    s0 += __shfl_xor_sync(0xffffffffu, s0, 1);
    s0 += __shfl_xor_sync(0xffffffffu, s0, 2);
    s1 += __shfl_xor_sync(0xffffffffu, s1, 1);
    s1 += __shfl_xor_sync(0xffffffffu, s1, 2);
    float* svb = (float*)(sm + SM_SV);
    if (m == 0) {
        svb[wn * 128 + wm * 16 + q] = s0;
        svb[wn * 128 + wm * 16 + q + 8] = s1;
    }
    __syncthreads();

    if (tid < nt) {
        float sv = svb[tid] + svb[128 + tid];
        int eid = seid[tid];
        const float4* EN = (const float4*)g_enew + (size_t)eid * 32;
        float sq = 0.f;
#pragma unroll 8
        for (int k4 = 0; k4 < 32; k4++) {
            float4 en = EN[k4];
            sq += en.x * en.x + en.y * en.y + en.z * en.z + en.w * en.w;
        }
        float L = sqrtf(sq);
        if (L > 1e-9f && sv > 0.f) {
            float r = 0.5f * sqrtf(L);
            float cf = sv * expf(-r / 0.3f) / (1.2f * L * sqrtf(L));
            float* fp = &g_facc[(size_t)sdst[tid] * DD];
#pragma unroll 8
            for (int k4 = 0; k4 < 32; k4++) {
                float4 en = EN[k4];
                atomicAdd(fp + k4 * 4 + 0, cf * en.x);
                atomicAdd(fp + k4 * 4 + 1, cf * en.y);
                atomicAdd(fp + k4 * 4 + 2, cf * en.z);
                atomicAdd(fp + k4 * 4 + 3, cf * en.w);
            }
        }
    }
}

// ================= node finalize =================
__global__ void k_final(const float* __restrict__ h, const float* __restrict__ p,
                        const float* __restrict__ dv, const float* __restrict__ dt,
                        float* __restrict__ out) {
    int w = threadIdx.x >> 5, l = threadIdx.x & 31;
    int n = blockIdx.x * 8 + w;
    int ix = n * 32 + l;
    const float4* V1 = (const float4*)g_proj[0];
    const float4* V2 = (const float4*)g_proj[1];
    const float4* P3 = (const float4*)g_proj[4];
    const float4* D1 = (const float4*)g_proj[5];
    const float4* D2 = (const float4*)g_proj[6];
    const float4* TH = (const float4*)g_proj[7];
    const float4* FA = (const float4*)g_facc;

    float4 v1 = V1[ix], v2 = V2[ix], p3 = P3[ix], d1 = D1[ix], d2 = D2[ix];
    float4 th = TH[ix], fa = FA[ix];
    float cnt = (float)g_cnt0[n];

    float4 f;
    f.x = (d1.x - v1.x) * (cnt * relu_(th.x)) + fa.x;
    f.y = (d1.y - v1.y) * (cnt * relu_(th.y)) + fa.y;
    f.z = (d1.z - v1.z) * (cnt * relu_(th.z)) + fa.z;
    f.w = (d1.w - v1.w) * (cnt * relu_(th.w)) + fa.w;

    float sq = f.x * f.x + f.y * f.y + f.z * f.z + f.w * f.w;
#pragma unroll
    for (int off = 16; off > 0; off >>= 1) sq += __shfl_xor_sync(0xffffffffu, sq, off);
    float inv = 1.f / (sqrtf(sq) + 1e-9f);

    float dtv = dt[n];
    float dtp = dtv + 0.5f * dtv * dtv;

    float4 hv = ((const float4*)h)[ix];
    float4 pv = ((const float4*)p)[ix];
    float4 dvv = ((const float4*)dv)[ix];

    float4 ho, po, dq;
    ho.x = hv.x + lrelu(v2.x + f.x * dtv);
    ho.y = hv.y + lrelu(v2.y + f.y * dtv);
    ho.z = hv.z + lrelu(v2.z + f.z * dtv);
    ho.w = hv.w + lrelu(v2.w + f.w * dtv);
    po.x = pv.x + lrelu(p3.x + f.x * dtp);
    po.y = pv.y + lrelu(p3.y + f.y * dtp);
    po.z = pv.z + lrelu(p3.z + f.z * dtp);
    po.w = pv.w + lrelu(p3.w + f.w * dtp);
    dq.x = dvv.x + lrelu(d2.x + f.x * inv);
    dq.y = dvv.y + lrelu(d2.y + f.y * inv);
    dq.z = dvv.z + lrelu(d2.z + f.z * inv);
    dq.w = dvv.w + lrelu(d2.w + f.w * inv);

    float4* outH = (float4*)out;
    float4* outP = (float4*)(out + (size_t)NN * DD + (size_t)EE * DD);
    float4* outD = (float4*)(out + 2 * (size_t)NN * DD + (size_t)EE * DD);
    outH[ix] = ho;
    outP[ix] = po;
    outD[ix] = dq;
}

// ================= launch =================
extern "C" void kernel_launch(void* const* d_in, const int* in_sizes, int n_in,
                              void* d_out, int out_size) {
    const float* h   = (const float*)d_in[0];
    const float* e   = (const float*)d_in[1];
    const float* p   = (const float*)d_in[2];
    const float* dv  = (const float*)d_in[3];
    const float* dt  = (const float*)d_in[4];
    const int* smask = (const int*)d_in[5];
    const int* src   = (const int*)d_in[6];
    const int* dst   = (const int*)d_in[7];
    const float* W_V1 = (const float*)d_in[8],  *b_V1 = (const float*)d_in[9];
    const float* W_V2 = (const float*)d_in[10], *b_V2 = (const float*)d_in[11];
    const float* W_E1 = (const float*)d_in[12], *b_E1 = (const float*)d_in[13];
    const float* W_P1 = (const float*)d_in[14], *b_P1 = (const float*)d_in[15];
    const float* W_P2 = (const float*)d_in[16], *b_P2 = (const float*)d_in[17];
    const float* W_P3 = (const float*)d_in[18], *b_P3 = (const float*)d_in[19];
    const float* W_D1 = (const float*)d_in[20], *b_D1 = (const float*)d_in[21];
    const float* W_D2 = (const float*)d_in[22], *b_D2 = (const float*)d_in[23];
    const float* W_V  = (const float*)d_in[24], *b_V  = (const float*)d_in[25];
    const float* W_T  = (const float*)d_in[26], *b_T  = (const float*)d_in[27];
    float* out = (float*)d_out;

    cudaFuncSetAttribute(k_nodeg, cudaFuncAttributeMaxDynamicSharedMemorySize, SM_TOTAL);
    cudaFuncSetAttribute(k_edgeA, cudaFuncAttributeMaxDynamicSharedMemorySize, SM_TOTAL);
    cudaFuncSetAttribute(k_edgeB, cudaFuncAttributeMaxDynamicSharedMemorySize, SM_TOTAL);

    k_zero<<<640, 256>>>();
    k_wbf<<<704, 256>>>(W_V1, W_V2, W_P1, W_P2, W_P3, W_D1, W_D2, W_E1, W_V, W_T);
    k_count<<<EE / 256, 256>>>(smask, dst);
    k_nodeg<<<dim3((NN + 127) / 128, 8), 512, SM_TOTAL>>>(h, p, dv, b_V1, b_V2, b_P1,
                                                          b_P2, b_P3, b_D1, b_D2, b_T);
    k_edgeA<<<EE / 128, 512, SM_TOTAL>>>(e, src, dst, smask, b_E1, out + (size_t)NN * DD);
    k_edgeB<<<EE / 128, 512, SM_TOTAL>>>(h, b_V, src, dst);
    k_final<<<NN / 8, 256>>>(h, p, dv, dt, out);
}

// round 5
// speedup vs baseline: 1.9491x; 1.1091x over previous
#include <cuda_runtime.h>
#include <cuda_bf16.h>
#include <cstdint>
#include <math.h>

#define NN 10000
#define EE 320000
#define DD 128

// ================= static device scratch =================
__device__ float g_proj[8][NN * DD];          // V1h V2h P1h P2h P3h D1h D2h Th
__device__ float g_enew[(size_t)EE * DD];
__device__ float g_facc[NN * DD];
__device__ int   g_cnt0[NN];
__device__ int   g_mlist[EE];
__device__ int   g_mcount;
// pre-split weight tiles in swizzled layout (32KB each):
// slots 0..6 node W (V1,V2,P1,P2,P3,D1,D2), 7 E1, 8 V, 9/10 = W_T halves
__device__ __align__(16) unsigned char g_wbh[11 * 32768];
__device__ __align__(16) unsigned char g_wbl[11 * 32768];

__device__ __forceinline__ float lrelu(float x) { return x > 0.f ? x : 0.01f * x; }
__device__ __forceinline__ float relu_(float x) { return x > 0.f ? x : 0.f; }

__device__ __forceinline__ uint32_t smem_u32(const void* p) {
    uint32_t a;
    asm("{ .reg .u64 t; cvta.to.shared.u64 t, %1; cvt.u32.u64 %0, t; }" : "=r"(a) : "l"(p));
    return a;
}
__device__ __forceinline__ uint32_t pack2(__nv_bfloat16 a, __nv_bfloat16 b) {
    __nv_bfloat162 t; t.x = a; t.y = b;
    return *reinterpret_cast<uint32_t*>(&t);
}

// swizzled byte offset inside a 128x128 bf16 tile (B tiles): row stride 256B
__device__ __forceinline__ uint32_t soff(int r, int c) {
    return (uint32_t)((r << 8) + ((((c >> 3) ^ (r & 7)) << 4) | ((c & 7) << 1)));
}
// swizzled byte offset inside a 128x64 bf16 tile (A half-tiles): row stride 128B
__device__ __forceinline__ uint32_t soff64(int r, int c) {
    return (uint32_t)((r << 7) + (((((c >> 3) ^ (r & 7)) & 7) << 4) | ((c & 7) << 1)));
}

__device__ __forceinline__ void ldsm4(uint32_t* r, uint32_t addr) {
    asm volatile("ldmatrix.sync.aligned.m8n8.x4.shared.b16 {%0,%1,%2,%3}, [%4];"
                 : "=r"(r[0]), "=r"(r[1]), "=r"(r[2]), "=r"(r[3]) : "r"(addr));
}
__device__ __forceinline__ void mma16816(float* d, const uint32_t* a,
                                         uint32_t b0, uint32_t b1) {
    asm volatile(
        "mma.sync.aligned.m16n8k16.row.col.f32.bf16.bf16.f32 "
        "{%0,%1,%2,%3}, {%4,%5,%6,%7}, {%8,%9}, {%0,%1,%2,%3};"
        : "+f"(d[0]), "+f"(d[1]), "+f"(d[2]), "+f"(d[3])
        : "r"(a[0]), "r"(a[1]), "r"(a[2]), "r"(a[3]), "r"(b0), "r"(b1));
}

// split 8 fp32 -> hi/lo bf16x2 quads
__device__ __forceinline__ void cvt8(float4 v0, float4 v1, uint4& hi, uint4& lo) {
    __nv_bfloat16 a0 = __float2bfloat16(v0.x), a1 = __float2bfloat16(v0.y);
    __nv_bfloat16 a2 = __float2bfloat16(v0.z), a3 = __float2bfloat16(v0.w);
    __nv_bfloat16 a4 = __float2bfloat16(v1.x), a5 = __float2bfloat16(v1.y);
    __nv_bfloat16 a6 = __float2bfloat16(v1.z), a7 = __float2bfloat16(v1.w);
    hi.x = pack2(a0, a1); hi.y = pack2(a2, a3);
    hi.z = pack2(a4, a5); hi.w = pack2(a6, a7);
    lo.x = pack2(__float2bfloat16(v0.x - __bfloat162float(a0)),
                 __float2bfloat16(v0.y - __bfloat162float(a1)));
    lo.y = pack2(__float2bfloat16(v0.z - __bfloat162float(a2)),
                 __float2bfloat16(v0.w - __bfloat162float(a3)));
    lo.z = pack2(__float2bfloat16(v1.x - __bfloat162float(a4)),
                 __float2bfloat16(v1.y - __bfloat162float(a5)));
    lo.w = pack2(__float2bfloat16(v1.z - __bfloat162float(a6)),
                 __float2bfloat16(v1.w - __bfloat162float(a7)));
}

// shared memory layout (102400 bytes total -> 2 CTAs/SM)
#define SM_BIAS 0
#define SM_ROWA 512     /* per-row src  */
#define SM_ROWB 1024    /* per-row dst  */
#define SM_ROWC 1536    /* per-row mask / eid */
#define SM_SV   2048    /* 2 x 128 partial row sums */
#define SM_AH   4096                 /* 128x64 bf16 hi  (16KB) */
#define SM_AL   (4096 + 16384)       /* 128x64 bf16 lo  (16KB) */
#define SM_BH   (4096 + 32768)       /* 128x128 bf16 hi (32KB) */
#define SM_BL   (4096 + 65536)       /* 128x128 bf16 lo (32KB) */
#define SM_C    4096    /* fp32 C 128x520B, overlays A + part of BH (post-GEMM) */
#define C_STRIDE 520
#define SM_TOTAL (4096 + 98304)

// ---- 3-term split GEMM over one K-half, warp tile 32(M) x 64(N), 8 warps ----
// wm = wid&3 (M block of 32), wn = wid>>2 (N half of 64)
// acc[mf][2*bn+p][*]: rows wm*32+mf*16+(lane>>2){,+8}, cols wn*64+bn*16+p*8..+7
__device__ __forceinline__ void gemm_half(uint32_t smb, int lane, int wm, int wn,
                                          int kh, float (&acc)[2][8][4]) {
    const int fr = lane & 15;
    const int fc = (lane >> 4) << 3;
    const int m0 = wm * 32;
    const int n0 = wn * 64;
#pragma unroll
    for (int ks = 0; ks < 4; ks++) {
        uint32_t aH[2][4], aL[2][4];
#pragma unroll
        for (int mf = 0; mf < 2; mf++) {
            ldsm4(aH[mf], smb + SM_AH + soff64(m0 + mf * 16 + fr, ks * 16 + fc));
            ldsm4(aL[mf], smb + SM_AL + soff64(m0 + mf * 16 + fr, ks * 16 + fc));
        }
        const int kc = kh * 64 + ks * 16 + fc;
#pragma unroll
        for (int bn = 0; bn < 4; bn++) {
            uint32_t bH[4], bL[4];
            ldsm4(bH, smb + SM_BH + soff(n0 + bn * 16 + fr, kc));
            ldsm4(bL, smb + SM_BL + soff(n0 + bn * 16 + fr, kc));
#pragma unroll
            for (int mf = 0; mf < 2; mf++) {
                mma16816(acc[mf][2 * bn],     aH[mf], bH[0], bH[2]);
                mma16816(acc[mf][2 * bn + 1], aH[mf], bH[1], bH[3]);
                mma16816(acc[mf][2 * bn],     aL[mf], bH[0], bH[2]);
                mma16816(acc[mf][2 * bn + 1], aL[mf], bH[1], bH[3]);
                mma16816(acc[mf][2 * bn],     aH[mf], bL[0], bL[2]);
                mma16816(acc[mf][2 * bn + 1], aH[mf], bL[1], bL[3]);
            }
        }
    }
}

__device__ __forceinline__ void store_C(char* sm, int lane, int wm, int wn,
                                        float (&acc)[2][8][4]) {
    int q = lane >> 2, m = lane & 3;
    char* base = sm + SM_C;
#pragma unroll
    for (int mf = 0; mf < 2; mf++) {
        int r0 = wm * 32 + mf * 16 + q;
#pragma unroll
        for (int j = 0; j < 8; j++) {
            int col = wn * 64 + j * 8 + m * 2;
            *(float2*)(base + r0 * C_STRIDE + col * 4) =
                make_float2(acc[mf][j][0], acc[mf][j][1]);
            *(float2*)(base + (r0 + 8) * C_STRIDE + col * 4) =
                make_float2(acc[mf][j][2], acc[mf][j][3]);
        }
    }
}

__device__ __forceinline__ void copy_B(char* sm, int slot, int tid) {
    const uint4* gh = (const uint4*)(g_wbh + slot * 32768);
    const uint4* gl = (const uint4*)(g_wbl + slot * 32768);
    uint4* bh = (uint4*)(sm + SM_BH);
    uint4* bl = (uint4*)(sm + SM_BL);
    for (int i = tid; i < 2048; i += 256) { bh[i] = gh[i]; bl[i] = gl[i]; }
}

// ================= prep kernels =================
__global__ void k_zero() {
    int i = blockIdx.x * blockDim.x + threadIdx.x;
    int stride = gridDim.x * blockDim.x;
    for (int t = i; t < NN * DD; t += stride) g_facc[t] = 0.f;
    for (int t = i; t < NN; t += stride) g_cnt0[t] = 0;
    if (i == 0) g_mcount = 0;
}

__global__ void k_wbf(const float* W0, const float* W1, const float* W2, const float* W3,
                      const float* W4, const float* W5, const float* W6, const float* W7,
                      const float* W8, const float* WT) {
    const float* Wp[9] = {W0, W1, W2, W3, W4, W5, W6, W7, W8};
    int i = blockIdx.x * blockDim.x + threadIdx.x;
    int stride = gridDim.x * blockDim.x;
    for (int t = i; t < 11 * 16384; t += stride) {
        int slot = t >> 14, r = t & 16383;
        int n = r >> 7, k = r & 127;
        float w;
        if (slot < 9) w = Wp[slot][n * 128 + k];
        else if (slot == 9) w = WT[n * 256 + k];
        else w = WT[n * 256 + 128 + k];
        __nv_bfloat16 hi = __float2bfloat16(w);
        __nv_bfloat16 lo = __float2bfloat16(w - __bfloat162float(hi));
        uint32_t off = (uint32_t)slot * 32768u + soff(n, k);
        *reinterpret_cast<__nv_bfloat16*>(g_wbh + off) = hi;
        *reinterpret_cast<__nv_bfloat16*>(g_wbl + off) = lo;
    }
}

__global__ void k_count(const int* __restrict__ smask, const int* __restrict__ dst) {
    int e = blockIdx.x * 256 + threadIdx.x;
    int lane = threadIdx.x & 31;
    int sm_ = smask[e];
    int d_ = dst[e];
    unsigned bal = __ballot_sync(0xffffffffu, sm_ == 1);
    if (sm_ == 0) atomicAdd(&g_cnt0[d_], 1);
    int lead = bal ? (__ffs(bal) - 1) : 0;
    int basec = 0;
    if (bal && lane == lead) basec = atomicAdd(&g_mcount, __popc(bal));
    basec = __shfl_sync(0xffffffffu, basec, lead);
    if (sm_ == 1) g_mlist[basec + __popc(bal & ((1u << lane) - 1u))] = e;
}

// ================= node GEMMs (8 outputs) =================
__global__ void __launch_bounds__(256, 2)
k_nodeg(const float* __restrict__ h, const float* __restrict__ p,
        const float* __restrict__ dv,
        const float* bV1, const float* bV2, const float* bP1,
        const float* bP2, const float* bP3, const float* bD1,
        const float* bD2, const float* bT) {
    extern __shared__ char sm[];
    uint32_t smb = smem_u32(sm);
    int tid = threadIdx.x, lane = tid & 31, wid = tid >> 5;
    int wm = wid & 3, wn = wid >> 2;
    int pair = blockIdx.y;
    int r0 = blockIdx.x * 128;

    const float* X0;
    const float* bias;
    int slot0;
    switch (pair) {
        case 0: X0 = h;  slot0 = 0; bias = bV1; break;
        case 1: X0 = h;  slot0 = 1; bias = bV2; break;
        case 2: X0 = p;  slot0 = 2; bias = bP1; break;
        case 3: X0 = p;  slot0 = 3; bias = bP2; break;
        case 4: X0 = p;  slot0 = 4; bias = bP3; break;
        case 5: X0 = dv; slot0 = 5; bias = bD1; break;
        case 6: X0 = dv; slot0 = 6; bias = bD2; break;
        default: X0 = h; slot0 = 9; bias = bT; break;
    }
    if (tid < 128) ((float*)(sm + SM_BIAS))[tid] = bias[tid];

    float acc[2][8][4];
#pragma unroll
    for (int mf = 0; mf < 2; mf++)
#pragma unroll
        for (int j = 0; j < 8; j++)
#pragma unroll
            for (int i = 0; i < 4; i++) acc[mf][j][i] = 0.f;

    int nph = (pair == 7) ? 2 : 1;
    for (int ph = 0; ph < nph; ph++) {
        const float* X = (pair == 7 && ph == 1) ? dv : X0;
        copy_B(sm, slot0 + ph, tid);
        for (int kh = 0; kh < 2; kh++) {
            for (int u = tid; u < 1024; u += 256) {
                int row = u >> 3, ch = u & 7;
                int g = r0 + row;
                float4 v0 = make_float4(0.f, 0.f, 0.f, 0.f), v1 = v0;
                if (g < NN) {
                    v0 = ((const float4*)X)[(size_t)g * 32 + kh * 16 + ch * 2];
                    v1 = ((const float4*)X)[(size_t)g * 32 + kh * 16 + ch * 2 + 1];
                }
                uint4 hi, lo; cvt8(v0, v1, hi, lo);
                uint32_t off = soff64(row, ch * 8);
                *(uint4*)(sm + SM_AH + off) = hi;
                *(uint4*)(sm + SM_AL + off) = lo;
            }
            __syncthreads();
            gemm_half(smb, lane, wm, wn, kh, acc);
            __syncthreads();
        }
    }
    store_C(sm, lane, wm, wn, acc);
    __syncthreads();

    float* outp = g_proj[pair];
    for (int u = tid; u < 4096; u += 256) {
        int row = u >> 5, c4 = u & 31;
        int g = r0 + row;
        if (g < NN) {
            float2 x = *(float2*)(sm + SM_C + row * C_STRIDE + c4 * 16);
            float2 y = *(float2*)(sm + SM_C + row * C_STRIDE + c4 * 16 + 8);
            float4 bv = *(float4*)(sm + SM_BIAS + c4 * 16);
            float4 o;
            o.x = x.x + bv.x; o.y = x.y + bv.y; o.z = y.x + bv.z; o.w = y.y + bv.w;
            ((float4*)outp)[(size_t)g * 32 + c4] = o;
        }
    }
}

// ================= edge pass A: E1e GEMM + e_new + e' output =================
__global__ void __launch_bounds__(256, 2)
k_edgeA(const float* __restrict__ e_in, const int* __restrict__ src,
        const int* __restrict__ dst, const int* __restrict__ smask,
        const float* __restrict__ bE1, float* __restrict__ e_out) {
    extern __shared__ char sm[];
    uint32_t smb = smem_u32(sm);
    int tid = threadIdx.x, lane = tid & 31, wid = tid >> 5;
    int wm = wid & 3, wn = wid >> 2;
    int e0 = blockIdx.x * 128;

    if (tid < 128) {
        ((float*)(sm + SM_BIAS))[tid] = bE1[tid];
        int eg = e0 + tid;
        ((int*)(sm + SM_ROWA))[tid] = src[eg];
        ((int*)(sm + SM_ROWB))[tid] = dst[eg];
        ((int*)(sm + SM_ROWC))[tid] = smask[eg];
    }
    copy_B(sm, 7, tid);

    float acc[2][8][4];
#pragma unroll
    for (int mf = 0; mf < 2; mf++)
#pragma unroll
        for (int j = 0; j < 8; j++)
#pragma unroll
            for (int i = 0; i < 4; i++) acc[mf][j][i] = 0.f;

    for (int kh = 0; kh < 2; kh++) {
        for (int u = tid; u < 1024; u += 256) {
            int row = u >> 3, ch = u & 7;
            float4 v0 = ((const float4*)e_in)[(size_t)(e0 + row) * 32 + kh * 16 + ch * 2];
            float4 v1 = ((const float4*)e_in)[(size_t)(e0 + row) * 32 + kh * 16 + ch * 2 + 1];
            uint4 hi, lo; cvt8(v0, v1, hi, lo);
            uint32_t off = soff64(row, ch * 8);
            *(uint4*)(sm + SM_AH + off) = hi;
            *(uint4*)(sm + SM_AL + off) = lo;
        }
        __syncthreads();
        gemm_half(smb, lane, wm, wn, kh, acc);
        __syncthreads();
    }
    store_C(sm, lane, wm, wn, acc);
    __syncthreads();

    const int* ssrc = (const int*)(sm + SM_ROWA);
    const int* sdst = (const int*)(sm + SM_ROWB);
    const int* smsk = (const int*)(sm + SM_ROWC);
    const float4* P1 = (const float4*)g_proj[2];
    const float4* P2 = (const float4*)g_proj[3];
    for (int u = tid; u < 4096; u += 256) {
        int row = u >> 5, c4 = u & 31;
        int eg = e0 + row;
        int s = ssrc[row], dd = sdst[row], msk = smsk[row];
        float2 x = *(float2*)(sm + SM_C + row * C_STRIDE + c4 * 16);
        float2 y = *(float2*)(sm + SM_C + row * C_STRIDE + c4 * 16 + 8);
        float4 bv = *(float4*)(sm + SM_BIAS + c4 * 16);
        float4 p1 = P1[(size_t)dd * 32 + c4];
        float4 p2 = P2[(size_t)s * 32 + c4];
        float4 ev = ((const float4*)e_in)[(size_t)eg * 32 + c4];
        float4 en;
        en.x = 0.5f * (p1.x - p2.x + x.x + bv.x);
        en.y = 0.5f * (p1.y - p2.y + x.y + bv.y);
        en.z = 0.5f * (p1.z - p2.z + y.x + bv.z);
        en.w = 0.5f * (p1.w - p2.w + y.y + bv.w);
        float4 o;
        o.x = ev.x + lrelu(en.x);
        o.y = ev.y + lrelu(en.y);
        o.z = ev.z + lrelu(en.z);
        o.w = ev.w + lrelu(en.w);
        ((float4*)e_out)[(size_t)eg * 32 + c4] = o;
        if (msk) ((float4*)g_enew)[(size_t)eg * 32 + c4] = en;
    }
}

// ================= edge pass B: masked V GEMM + fab atomics =================
__global__ void __launch_bounds__(256, 2)
k_edgeB(const float* __restrict__ h, const float* __restrict__ bV,
        const int* __restrict__ src, const int* __restrict__ dst) {
    extern __shared__ char sm[];
    uint32_t smb = smem_u32(sm);
    int tid = threadIdx.x, lane = tid & 31, wid = tid >> 5;
    int wm = wid & 3, wn = wid >> 2;
    int mc = g_mcount;
    int base = blockIdx.x * 128;
    if (base >= mc) return;
    int nt = min(128, mc - base);

    int* seid = (int*)(sm + SM_ROWC);
    int* ssrc = (int*)(sm + SM_ROWA);
    int* sdst = (int*)(sm + SM_ROWB);
    if (tid < 128) {
        ((float*)(sm + SM_BIAS))[tid] = bV[tid];
        int eid = (tid < nt) ? g_mlist[base + tid] : -1;
        seid[tid] = eid;
        ssrc[tid] = (eid >= 0) ? src[eid] : 0;
        sdst[tid] = (eid >= 0) ? dst[eid] : 0;
    }
    copy_B(sm, 8, tid);
    __syncthreads();

    float acc[2][8][4];
#pragma unroll
    for (int mf = 0; mf < 2; mf++)
#pragma unroll
        for (int j = 0; j < 8; j++)
#pragma unroll
            for (int i = 0; i < 4; i++) acc[mf][j][i] = 0.f;

    for (int kh = 0; kh < 2; kh++) {
        for (int u = tid; u < 1024; u += 256) {
            int row = u >> 3, ch = u & 7;
            float4 v0 = make_float4(0.f, 0.f, 0.f, 0.f), v1 = v0;
            if (row < nt) {
                float4 hs0 = ((const float4*)h)[(size_t)ssrc[row] * 32 + kh * 16 + ch * 2];
                float4 hs1 = ((const float4*)h)[(size_t)ssrc[row] * 32 + kh * 16 + ch * 2 + 1];
                float4 hd0 = ((const float4*)h)[(size_t)sdst[row] * 32 + kh * 16 + ch * 2];
                float4 hd1 = ((const float4*)h)[(size_t)sdst[row] * 32 + kh * 16 + ch * 2 + 1];
                v0.x = hs0.x * hd0.x; v0.y = hs0.y * hd0.y;
                v0.z = hs0.z * hd0.z; v0.w = hs0.w * hd0.w;
                v1.x = hs1.x * hd1.x; v1.y = hs1.y * hd1.y;
                v1.z = hs1.z * hd1.z; v1.w = hs1.w * hd1.w;
            }
            uint4 hi, lo; cvt8(v0, v1, hi, lo);
            uint32_t off = soff64(row, ch * 8);
            *(uint4*)(sm + SM_AH + off) = hi;
            *(uint4*)(sm + SM_AL + off) = lo;
        }
        __syncthreads();
        gemm_half(smb, lane, wm, wn, kh, acc);
        __syncthreads();
    }

    // partial row-sums of relu(acc + bias): this warp covers cols wn*64..+63
    const float* bias_s = (const float*)(sm + SM_BIAS);
    int q = lane >> 2, m = lane & 3;
    float s[2][2] = {{0.f, 0.f}, {0.f, 0.f}};
#pragma unroll
    for (int mf = 0; mf < 2; mf++)
#pragma unroll
        for (int j = 0; j < 8; j++) {
            float b0 = bias_s[wn * 64 + j * 8 + m * 2];
            float b1 = bias_s[wn * 64 + j * 8 + m * 2 + 1];
            s[mf][0] += relu_(acc[mf][j][0] + b0) + relu_(acc[mf][j][1] + b1);
            s[mf][1] += relu_(acc[mf][j][2] + b0) + relu_(acc[mf][j][3] + b1);
        }
#pragma unroll
    for (int mf = 0; mf < 2; mf++) {
        s[mf][0] += __shfl_xor_sync(0xffffffffu, s[mf][0], 1);
        s[mf][0] += __shfl_xor_sync(0xffffffffu, s[mf][0], 2);
        s[mf][1] += __shfl_xor_sync(0xffffffffu, s[mf][1], 1);
        s[mf][1] += __shfl_xor_sync(0xffffffffu, s[mf][1], 2);
    }
    float* svb = (float*)(sm + SM_SV);
    if (m == 0) {
#pragma unroll
        for (int mf = 0; mf < 2; mf++) {
            svb[wn * 128 + wm * 32 + mf * 16 + q] = s[mf][0];
            svb[wn * 128 + wm * 32 + mf * 16 + q + 8] = s[mf][1];
        }
    }
    __syncthreads();

    if (tid < nt) {
        float sv = svb[tid] + svb[128 + tid];
        int eid = seid[tid];
        const float4* EN = (const float4*)g_enew + (size_t)eid * 32;
        float sq = 0.f;
#pragma unroll 8
        for (int k4 = 0; k4 < 32; k4++) {
            float4 en = EN[k4];
            sq += en.x * en.x + en.y * en.y + en.z * en.z + en.w * en.w;
        }
        float L = sqrtf(sq);
        if (L > 1e-9f && sv > 0.f) {
            float r = 0.5f * sqrtf(L);
            float cf = sv * expf(-r / 0.3f) / (1.2f * L * sqrtf(L));
            float* fp = &g_facc[(size_t)sdst[tid] * DD];
#pragma unroll 8
            for (int k4 = 0; k4 < 32; k4++) {
                float4 en = EN[k4];
                atomicAdd(fp + k4 * 4 + 0, cf * en.x);
                atomicAdd(fp + k4 * 4 + 1, cf * en.y);
                atomicAdd(fp + k4 * 4 + 2, cf * en.z);
                atomicAdd(fp + k4 * 4 + 3, cf * en.w);
            }
        }
    }
}

// ================= node finalize =================
__global__ void k_final(const float* __restrict__ h, const float* __restrict__ p,
                        const float* __restrict__ dv, const float* __restrict__ dt,
                        float* __restrict__ out) {
    int w = threadIdx.x >> 5, l = threadIdx.x & 31;
    int n = blockIdx.x * 8 + w;
    int ix = n * 32 + l;
    const float4* V1 = (const float4*)g_proj[0];
    const float4* V2 = (const float4*)g_proj[1];
    const float4* P3 = (const float4*)g_proj[4];
    const float4* D1 = (const float4*)g_proj[5];
    const float4* D2 = (const float4*)g_proj[6];
    const float4* TH = (const float4*)g_proj[7];
    const float4* FA = (const float4*)g_facc;

    float4 v1 = V1[ix], v2 = V2[ix], p3 = P3[ix], d1 = D1[ix], d2 = D2[ix];
    float4 th = TH[ix], fa = FA[ix];
    float cnt = (float)g_cnt0[n];

    float4 f;
    f.x = (d1.x - v1.x) * (cnt * relu_(th.x)) + fa.x;
    f.y = (d1.y - v1.y) * (cnt * relu_(th.y)) + fa.y;
    f.z = (d1.z - v1.z) * (cnt * relu_(th.z)) + fa.z;
    f.w = (d1.w - v1.w) * (cnt * relu_(th.w)) + fa.w;

    float sq = f.x * f.x + f.y * f.y + f.z * f.z + f.w * f.w;
#pragma unroll
    for (int off = 16; off > 0; off >>= 1) sq += __shfl_xor_sync(0xffffffffu, sq, off);
    float inv = 1.f / (sqrtf(sq) + 1e-9f);

    float dtv = dt[n];
    float dtp = dtv + 0.5f * dtv * dtv;

    float4 hv = ((const float4*)h)[ix];
    float4 pv = ((const float4*)p)[ix];
    float4 dvv = ((const float4*)dv)[ix];

    float4 ho, po, dq;
    ho.x = hv.x + lrelu(v2.x + f.x * dtv);
    ho.y = hv.y + lrelu(v2.y + f.y * dtv);
    ho.z = hv.z + lrelu(v2.z + f.z * dtv);
    ho.w = hv.w + lrelu(v2.w + f.w * dtv);
    po.x = pv.x + lrelu(p3.x + f.x * dtp);
    po.y = pv.y + lrelu(p3.y + f.y * dtp);
    po.z = pv.z + lrelu(p3.z + f.z * dtp);
    po.w = pv.w + lrelu(p3.w + f.w * dtp);
    dq.x = dvv.x + lrelu(d2.x + f.x * inv);
    dq.y = dvv.y + lrelu(d2.y + f.y * inv);
    dq.z = dvv.z + lrelu(d2.z + f.z * inv);
    dq.w = dvv.w + lrelu(d2.w + f.w * inv);

    float4* outH = (float4*)out;
    float4* outP = (float4*)(out + (size_t)NN * DD + (size_t)EE * DD);
    float4* outD = (float4*)(out + 2 * (size_t)NN * DD + (size_t)EE * DD);
    outH[ix] = ho;
    outP[ix] = po;
    outD[ix] = dq;
}

// ================= launch =================
extern "C" void kernel_launch(void* const* d_in, const int* in_sizes, int n_in,
                              void* d_out, int out_size) {
    const float* h   = (const float*)d_in[0];
    const float* e   = (const float*)d_in[1];
    const float* p   = (const float*)d_in[2];
    const float* dv  = (const float*)d_in[3];
    const float* dt  = (const float*)d_in[4];
    const int* smask = (const int*)d_in[5];
    const int* src   = (const int*)d_in[6];
    const int* dst   = (const int*)d_in[7];
    const float* W_V1 = (const float*)d_in[8],  *b_V1 = (const float*)d_in[9];
    const float* W_V2 = (const float*)d_in[10], *b_V2 = (const float*)d_in[11];
    const float* W_E1 = (const float*)d_in[12], *b_E1 = (const float*)d_in[13];
    const float* W_P1 = (const float*)d_in[14], *b_P1 = (const float*)d_in[15];
    const float* W_P2 = (const float*)d_in[16], *b_P2 = (const float*)d_in[17];
    const float* W_P3 = (const float*)d_in[18], *b_P3 = (const float*)d_in[19];
    const float* W_D1 = (const float*)d_in[20], *b_D1 = (const float*)d_in[21];
    const float* W_D2 = (const float*)d_in[22], *b_D2 = (const float*)d_in[23];
    const float* W_V  = (const float*)d_in[24], *b_V  = (const float*)d_in[25];
    const float* W_T  = (const float*)d_in[26], *b_T  = (const float*)d_in[27];
    float* out = (float*)d_out;

    cudaFuncSetAttribute(k_nodeg, cudaFuncAttributeMaxDynamicSharedMemorySize, SM_TOTAL);
    cudaFuncSetAttribute(k_edgeA, cudaFuncAttributeMaxDynamicSharedMemorySize, SM_TOTAL);
    cudaFuncSetAttribute(k_edgeB, cudaFuncAttributeMaxDynamicSharedMemorySize, SM_TOTAL);

    k_zero<<<640, 256>>>();
    k_wbf<<<704, 256>>>(W_V1, W_V2, W_P1, W_P2, W_P3, W_D1, W_D2, W_E1, W_V, W_T);
    k_count<<<EE / 256, 256>>>(smask, dst);
    k_nodeg<<<dim3((NN + 127) / 128, 8), 256, SM_TOTAL>>>(h, p, dv, b_V1, b_V2, b_P1,
                                                          b_P2, b_P3, b_D1, b_D2, b_T);
    k_edgeA<<<EE / 128, 256, SM_TOTAL>>>(e, src, dst, smask, b_E1, out + (size_t)NN * DD);
    k_edgeB<<<EE / 128, 256, SM_TOTAL>>>(h, b_V, src, dst);
    k_final<<<NN / 8, 256>>>(h, p, dv, dt, out);
}